// round 8
// baseline (speedup 1.0000x reference)
#include <cuda_runtime.h>
#include <cuda_bf16.h>
#include <math.h>
#include <stdint.h>

#define B  32
#define LX 64
#define TT 64
#define D  1024
#define V  32000
#define KP 3072
#define GRIDN 128
// ring: 3 mbarriers (32B) | A stages 3x4096 | B stages 3x8192
#define ABASE 32
#define BBASE 12320
#define RINGSZ 36896

// ------------------- device globals --------------------------------------------
__device__ float g_c[B * D];
__device__ float g_gatesp2[4 * 64 * 4096];
__device__ float g_hprojp2[16 * 64 * 1024];
__device__ float g_prep2[16 * 64 * 1024];
// step-GEMM A operands, chunk-block layout [chunk][64][32] (4KB blocks)
__device__ __align__(16) __nv_bfloat16 g_A2g[256 * 64 * 32];
__device__ __align__(16) __nv_bfloat16 g_A2h[64 * 64 * 32];
__device__ __align__(16) __nv_bfloat16 g_A2p[192 * 64 * 32];
// logits operands (row-major, unchanged)
__device__ __align__(16) __nv_bfloat16 g_Abf[(TT * B) * KP];
__device__ __align__(16) __nv_bfloat16 g_Bbf[(size_t)V * KP];
// weights, chunk-block layout [coltile][chunk][128][32] (8KB blocks)
__device__ __align__(16) __nv_bfloat16 g_Wg2[(size_t)32 * 256 * 128 * 32];
__device__ __align__(16) __nv_bfloat16 g_Wh2[8 * 64 * 128 * 32];
__device__ __align__(16) __nv_bfloat16 g_Wp2[8 * 192 * 128 * 32];
__device__ unsigned g_arrive;
__device__ volatile unsigned g_release;

// ------------------- helpers -----------------------------------------------------
__device__ __forceinline__ float fast_tanh(float x) {
    float e = __expf(2.f * x);
    return 1.f - __fdividef(2.f, e + 1.f);
}
__device__ __forceinline__ uint32_t smem_u32(const void* p) {
    uint32_t a;
    asm("{ .reg .u64 t; cvta.to.shared.u64 t, %1; cvt.u32.u64 %0, t; }" : "=r"(a) : "l"(p));
    return a;
}
__device__ __forceinline__ void cpasync16(uint32_t dst, const void* src) {
    asm volatile("cp.async.cg.shared.global [%0], [%1], 16;" :: "r"(dst), "l"(src));
}
__device__ __forceinline__ void ldm_x4(uint32_t* r, uint32_t addr) {
    asm volatile("ldmatrix.sync.aligned.m8n8.x4.shared.b16 {%0,%1,%2,%3}, [%4];"
        : "=r"(r[0]), "=r"(r[1]), "=r"(r[2]), "=r"(r[3]) : "r"(addr));
}
__device__ __forceinline__ void mma_bf16(float* c, const uint32_t* a, const uint32_t* b) {
    asm volatile("mma.sync.aligned.m16n8k16.row.col.f32.bf16.bf16.f32 "
        "{%0,%1,%2,%3}, {%4,%5,%6,%7}, {%8,%9}, {%0,%1,%2,%3};"
        : "+f"(c[0]), "+f"(c[1]), "+f"(c[2]), "+f"(c[3])
        : "r"(a[0]), "r"(a[1]), "r"(a[2]), "r"(a[3]), "r"(b[0]), "r"(b[1]));
}
__device__ __forceinline__ void split_bf(float v, __nv_bfloat16& hi, __nv_bfloat16& lo) {
    hi = __float2bfloat16_rn(v);
    lo = __float2bfloat16_rn(v - __bfloat162float(hi));
}
// swizzled element offset within a [row][32] chunk-block row
__device__ __forceinline__ int swoff(int row, int kin) {
    return ((((kin >> 3) ^ ((row >> 1) & 3)) << 3) | (kin & 7));
}
__device__ __forceinline__ void a2st(__nv_bfloat16* base, int row, int k, __nv_bfloat16 v) {
    base[((k >> 5) * 64 + row) * 32 + swoff(row, k & 31)] = v;
}
__device__ __forceinline__ void w2st(__nv_bfloat16* base, int nch, int j, int k,
                                     __nv_bfloat16 v) {
    base[(size_t)(((j >> 7) * nch + (k >> 5)) * 128 + (j & 127)) * 32
         + swoff(j & 127, k & 31)] = v;
}
// ------------------- bulk copy + mbarrier ------------------------------------------
__device__ __forceinline__ void bulk_g2s(uint32_t dst, const void* src, uint32_t bytes,
                                         uint32_t mbar) {
    asm volatile(
        "cp.async.bulk.shared::cluster.global.mbarrier::complete_tx::bytes [%0], [%1], %2, [%3];"
        :: "r"(dst), "l"(src), "r"(bytes), "r"(mbar) : "memory");
}
__device__ __forceinline__ void mbar_expect(uint32_t mbar, uint32_t bytes) {
    asm volatile("mbarrier.arrive.expect_tx.shared.b64 _, [%0], %1;"
                 :: "r"(mbar), "r"(bytes) : "memory");
}
__device__ __forceinline__ void mbar_init1(uint32_t mbar) {
    asm volatile("mbarrier.init.shared.b64 [%0], 1;" :: "r"(mbar) : "memory");
}
__device__ __forceinline__ void mbar_wait(uint32_t mbar, uint32_t parity) {
    asm volatile(
        "{\n\t.reg .pred P;\n"
        "W%=:\n\t"
        "mbarrier.try_wait.parity.shared.b64 P, [%0], %1;\n\t"
        "@P bra D%=;\n\t"
        "bra W%=;\n"
        "D%=:\n\t}"
        :: "r"(mbar), "r"(parity) : "memory");
}
// ------------------- grid barrier ---------------------------------------------------
__device__ __forceinline__ void gridbar(unsigned gen) {
    asm volatile("fence.proxy.async;" ::: "memory");
    __threadfence();
    __syncthreads();
    if (threadIdx.x == 0) {
        unsigned a = atomicAdd(&g_arrive, 1u) + 1u;
        if (a == gen * GRIDN) {
            atomicExch((unsigned*)&g_release, gen);
        } else {
            while (g_release < gen) __nanosleep(32);
        }
    }
    __syncthreads();
}

// ------------------- init -----------------------------------------------------------
__global__ void k_init0(const float* __restrict__ h0, const float* __restrict__ c0,
                        const float* __restrict__ word_emb,
                        const int* __restrict__ y_train) {
    int i = blockIdx.x * 256 + threadIdx.x;
    if (i == 0) { g_arrive = 0; g_release = 0; }
    if (i < 64 * 8192) {                 // gates A2 for t=0
        int r = i >> 13, k = i & 8191;
        int b = r & 31;
        bool isLo = r >= 32;
        int ks = (k < 4096) ? k : k - 4096;
        float v = 0.f;
        bool zero = (isLo && k >= 4096);
        if (!zero) {
            if (ks < 1024) {
                int y = y_train[b * TT + 0];
                v = word_emb[(size_t)y * D + ks];
            } else if (ks < 3072) {
                v = 0.f;
            } else {
                v = h0[b * D + (ks - 3072)];
            }
        }
        __nv_bfloat16 hi, lo; split_bf(v, hi, lo);
        a2st(g_A2g, r, k, zero ? __float2bfloat16_rn(0.f) : (isLo ? lo : hi));
        return;
    }
    int j = i - 64 * 8192;
    if (j < 32 * 1024) {                 // A2h lo-zero rows 32-63, k [1024,2048)
        int r = 32 + (j >> 10), k = 1024 + (j & 1023);
        a2st(g_A2h, r, k, __float2bfloat16_rn(0.f));
        return;
    }
    j -= 32 * 1024;
    if (j < 32 * 3072) {                 // A2p lo-zero rows 32-63, k [3072,6144)
        int r = 32 + j / 3072, k = 3072 + j % 3072;
        a2st(g_A2p, r, k, __float2bfloat16_rn(0.f));
        return;
    }
    j -= 32 * 3072;
    if (j < B * D) g_c[j] = c0[j];
}

// ------------------- weight conversions ----------------------------------------------
__global__ void k_convB(const float* __restrict__ RW) {
    int i = blockIdx.x * 256 + threadIdx.x;
    float v = RW[i];
    int r = i >> 10, d = i & 1023;
    __nv_bfloat16 hi, lo; split_bf(v, hi, lo);
    __nv_bfloat16* row = g_Bbf + (size_t)r * KP;
    row[d] = hi; row[1024 + d] = hi; row[2048 + d] = lo;
}
__global__ void k_convWg(const float* __restrict__ Wih, const float* __restrict__ Whh) {
    int k = blockIdx.x * 256 + threadIdx.x;
    int j = blockIdx.y;
    float v = (k < 3072) ? Wih[(size_t)j * 3072 + k] : Whh[(size_t)j * 1024 + (k - 3072)];
    __nv_bfloat16 hi, lo; split_bf(v, hi, lo);
    w2st(g_Wg2, 256, j, k, hi);
    w2st(g_Wg2, 256, j, 4096 + k, lo);
}
__global__ void k_convWh(const float* __restrict__ Wt) {
    int k = blockIdx.x * 256 + threadIdx.x;
    int j = blockIdx.y;
    float v = Wt[(size_t)j * 1024 + k];
    __nv_bfloat16 hi, lo; split_bf(v, hi, lo);
    w2st(g_Wh2, 64, j, k, hi);
    w2st(g_Wh2, 64, j, 1024 + k, lo);
}
__global__ void k_convWp(const float* __restrict__ Cw) {
    int k = blockIdx.x * 256 + threadIdx.x;
    int j = blockIdx.y;
    float v = Cw[(size_t)j * 3072 + k];
    __nv_bfloat16 hi, lo; split_bf(v, hi, lo);
    w2st(g_Wp2, 192, j, k, hi);
    w2st(g_Wp2, 192, j, 3072 + k, lo);
}

// ------------------- bulk-fed 64xK @ Kx128 MMA phase ----------------------------------
__device__ void mma_phase_bulk(uint32_t sb, unsigned& gc,
        const __nv_bfloat16* __restrict__ Ablk,
        const __nv_bfloat16* __restrict__ Bblk,
        float* __restrict__ part, int ncols,
        int nch, int chunk0, int col0, int split) {
    int tid = threadIdx.x;
    int lane = tid & 31, wid = tid >> 5;
    int warpM = wid & 1, warpN = wid >> 1;

    int a_row = (lane & 7) + ((lane >> 3) & 1) * 8;
    int ca0 = lane >> 4;
    int b_row = (lane & 7) + (lane >> 4) * 8;
    int cb0 = (lane >> 3) & 1;
    int rA[2], sA_[2], rB[2], sB_[2];
#pragma unroll
    for (int mt = 0; mt < 2; mt++) {
        int r = warpM * 32 + mt * 16 + a_row;
        rA[mt] = r * 64; sA_[mt] = (r >> 1) & 3;
    }
#pragma unroll
    for (int p = 0; p < 2; p++) {
        int r = warpN * 32 + p * 16 + b_row;
        rB[p] = r * 64; sB_[p] = (r >> 1) & 3;
    }

    float acc[2][4][4] = {};

#define ISSUE(j) do { if (tid == 0) { \
        unsigned idx_ = gc + (unsigned)(j); uint32_t st_ = idx_ % 3u; \
        uint32_t mb_ = sb + st_ * 8u; \
        mbar_expect(mb_, 12288u); \
        bulk_g2s(sb + ABASE + st_ * 4096u, Ablk + (size_t)(chunk0 + (j)) * 2048, 4096u, mb_); \
        bulk_g2s(sb + BBASE + st_ * 8192u, Bblk + (size_t)(chunk0 + (j)) * 4096, 8192u, mb_); \
    } } while (0)

    ISSUE(0);
    ISSUE(1);
    for (int i = 0; i < nch; i++) {
        unsigned idx = gc + (unsigned)i;
        uint32_t st = idx % 3u;
        mbar_wait(sb + st * 8u, (idx / 3u) & 1u);
        uint32_t aOff = sb + ABASE + st * 4096u;
        uint32_t bOff = sb + BBASE + st * 8192u;
#pragma unroll
        for (int k16 = 0; k16 < 2; k16++) {
            int ca = ca0 + 2 * k16, cb = cb0 + 2 * k16;
            uint32_t a0[4], a1[4], bb[2][4];
            ldm_x4(a0, aOff + rA[0] + ((ca ^ sA_[0]) << 4));
            ldm_x4(a1, aOff + rA[1] + ((ca ^ sA_[1]) << 4));
            ldm_x4(bb[0], bOff + rB[0] + ((cb ^ sB_[0]) << 4));
            ldm_x4(bb[1], bOff + rB[1] + ((cb ^ sB_[1]) << 4));
#pragma unroll
            for (int nt = 0; nt < 4; nt++) {
                mma_bf16(acc[0][nt], a0, &bb[nt >> 1][(nt & 1) * 2]);
                mma_bf16(acc[1][nt], a1, &bb[nt >> 1][(nt & 1) * 2]);
            }
        }
        __syncthreads();
        if (i + 2 < nch) ISSUE(i + 2);
    }
    gc += (unsigned)nch;
#undef ISSUE

    int grp = lane >> 2, tig = lane & 3;
#pragma unroll
    for (int mt = 0; mt < 2; mt++) {
        int m1 = warpM * 32 + mt * 16 + grp;
        int m2 = m1 + 8;
        float* p1 = part + (size_t)(split * 64 + m1) * ncols + col0 + warpN * 32;
        float* p2 = part + (size_t)(split * 64 + m2) * ncols + col0 + warpN * 32;
#pragma unroll
        for (int nt = 0; nt < 4; nt++) {
            int n = nt * 8 + tig * 2;
            *(float2*)(p1 + n) = make_float2(acc[mt][nt][0], acc[mt][nt][1]);
            *(float2*)(p2 + n) = make_float2(acc[mt][nt][2], acc[mt][nt][3]);
        }
    }
}

// ------------------- scalar phase work ------------------------------------------------
__device__ void cell_work(int bid, const float* __restrict__ b_ih,
                          const float* __restrict__ b_hh) {
    int id = bid * 256 + threadIdx.x;
    int m = id >> 10, d = id & 1023;
    float ig = b_ih[d]        + b_hh[d];
    float fg = b_ih[1024 + d] + b_hh[1024 + d];
    float gg = b_ih[2048 + d] + b_hh[2048 + d];
    float og = b_ih[3072 + d] + b_hh[3072 + d];
#pragma unroll
    for (int s = 0; s < 4; s++) {
        const float* p0 = g_gatesp2 + (size_t)(s * 64 + m) * 4096;
        const float* p1 = g_gatesp2 + (size_t)(s * 64 + 32 + m) * 4096;
        ig += __ldcg(p0 + d)        + __ldcg(p1 + d);
        fg += __ldcg(p0 + 1024 + d) + __ldcg(p1 + 1024 + d);
        gg += __ldcg(p0 + 2048 + d) + __ldcg(p1 + 2048 + d);
        og += __ldcg(p0 + 3072 + d) + __ldcg(p1 + 3072 + d);
    }
    float si = 1.f / (1.f + expf(-ig));
    float sf = 1.f / (1.f + expf(-fg));
    float so = 1.f / (1.f + expf(-og));
    float c = sf * __ldcg(&g_c[id]) + si * tanhf(gg);
    g_c[id] = c;
    float h = so * tanhf(c);
    __nv_bfloat16 hh, hl; split_bf(h, hh, hl);
    a2st(g_A2h, m, d, hh);        a2st(g_A2h, m, 1024 + d, hh);  a2st(g_A2h, 32 + m, d, hl);
    a2st(g_A2p, m, d, hh);        a2st(g_A2p, m, 3072 + d, hh);  a2st(g_A2p, 32 + m, d, hl);
    a2st(g_A2g, m, 3072 + d, hh); a2st(g_A2g, m, 7168 + d, hh);
    a2st(g_A2g, 32 + m, 3072 + d, hl);
}

__device__ void pretanh_work(int t, int bid) {
    int id = bid * 256 + threadIdx.x;
    int m = id >> 10, d = id & 1023;
    float v = 0.f;
#pragma unroll
    for (int s = 0; s < 16; s++) {
        v += __ldcg(&g_prep2[(size_t)(s * 64 + m) * 1024 + d]);
        v += __ldcg(&g_prep2[(size_t)(s * 64 + 32 + m) * 1024 + d]);
    }
    v = tanhf(v);
    int row = t * B + m;
    __nv_bfloat16 hi, lo; split_bf(v, hi, lo);
    __nv_bfloat16* arow = g_Abf + (size_t)row * KP;
    arow[d] = hi; arow[1024 + d] = lo; arow[2048 + d] = hi;
}

__device__ void attn_work(int b, float* s_hp, float* s_wl,
                          const float* __restrict__ x_enc,
                          const float* __restrict__ x_enc_k,
                          const unsigned char* __restrict__ xm,
                          const float* __restrict__ w_trg_b,
                          const float* __restrict__ w_att,
                          const float* __restrict__ w_att_b) {
    int tid = threadIdx.x;
    int lane = tid & 31, wd = tid >> 5;
    for (int d = tid; d < 1024; d += 256) {
        float sum = w_trg_b[d];
#pragma unroll
        for (int s = 0; s < 16; s++) {
            sum += __ldcg(&g_hprojp2[(size_t)(s * 64 + b) * 1024 + d]);
            sum += __ldcg(&g_hprojp2[(size_t)(s * 64 + 32 + b) * 1024 + d]);
        }
        s_hp[d] = sum;
    }
    __syncthreads();
    for (int l = wd; l < LX; l += 8) {
        const float* xk = x_enc_k + ((size_t)b * LX + l) * D;
        float s = 0.f;
#pragma unroll 8
        for (int i = 0; i < 32; i++) {
            int d = lane + i * 32;
            s += fast_tanh(xk[d] + s_hp[d]) * w_att[d];
        }
#pragma unroll
        for (int off = 16; off; off >>= 1) s += __shfl_xor_sync(0xffffffffu, s, off);
        if (lane == 0) {
            float tot = s + w_att_b[0];
            if (xm[b * LX + l]) tot = -1e9f;
            s_wl[l] = tot;
        }
    }
    __syncthreads();
    if (tid == 0) {
        float mx = -1e30f;
        for (int l = 0; l < LX; l++) mx = fmaxf(mx, s_wl[l]);
        float z = 0.f;
        for (int l = 0; l < LX; l++) { float e = expf(s_wl[l] - mx); s_wl[l] = e; z += e; }
        float inv = 1.f / z;
        for (int l = 0; l < LX; l++) s_wl[l] *= inv;
    }
    __syncthreads();
    {
        int d2 = tid * 8;
        const float* xe = x_enc + (size_t)b * LX * 2048 + d2;
        float f[8];
#pragma unroll
        for (int q = 0; q < 8; q++) f[q] = 0.f;
#pragma unroll 8
        for (int l = 0; l < LX; l++) {
            float w = s_wl[l];
            float4 x0 = *(const float4*)(xe + (size_t)l * 2048);
            float4 x1 = *(const float4*)(xe + (size_t)l * 2048 + 4);
            f[0] += w * x0.x; f[1] += w * x0.y; f[2] += w * x0.z; f[3] += w * x0.w;
            f[4] += w * x1.x; f[5] += w * x1.y; f[6] += w * x1.z; f[7] += w * x1.w;
        }
#pragma unroll
        for (int q = 0; q < 8; q++) {
            int dd = 1024 + d2 + q;
            __nv_bfloat16 hi, lo; split_bf(f[q], hi, lo);
            a2st(g_A2p, b, dd, hi);       a2st(g_A2p, b, 3072 + dd, hi);
            a2st(g_A2p, 32 + b, dd, lo);
            a2st(g_A2g, b, dd, hi);       a2st(g_A2g, b, 4096 + dd, hi);
            a2st(g_A2g, 32 + b, dd, lo);
        }
    }
}

__device__ void emb_prefetch(int b, int tnext, const float* __restrict__ word_emb,
                             const int* __restrict__ y_train) {
    int d = threadIdx.x * 4;
    int y = y_train[b * TT + tnext];
    float4 v = *(const float4*)(word_emb + (size_t)y * D + d);
    float vv[4] = {v.x, v.y, v.z, v.w};
#pragma unroll
    for (int q = 0; q < 4; q++) {
        __nv_bfloat16 hi, lo; split_bf(vv[q], hi, lo);
        int k = d + q;
        a2st(g_A2g, b, k, hi); a2st(g_A2g, b, 4096 + k, hi); a2st(g_A2g, 32 + b, k, lo);
    }
}

// ------------------- persistent step kernel --------------------------------------------
__global__ void __launch_bounds__(256, 1) k_steps(
    const float* __restrict__ x_enc, const float* __restrict__ x_enc_k,
    const unsigned char* __restrict__ xm, const int* __restrict__ y_train,
    const float* __restrict__ word_emb,
    const float* __restrict__ b_ih, const float* __restrict__ b_hh,
    const float* __restrict__ w_trg_b, const float* __restrict__ w_att,
    const float* __restrict__ w_att_b) {
    __shared__ __align__(128) char s_ring[RINGSZ];
    __shared__ float s_hp[1024];
    __shared__ float s_wl[LX];
    uint32_t sb = smem_u32(s_ring);
    int bid = blockIdx.x;
    unsigned gen = 0, gc = 0;

    if (threadIdx.x == 0) { mbar_init1(sb); mbar_init1(sb + 8); mbar_init1(sb + 16); }
    __syncthreads();

    for (int t = 0; t < TT; t++) {
        if (t > 0) pretanh_work(t - 1, bid);
        mma_phase_bulk(sb, gc, g_A2g,
                       g_Wg2 + (size_t)(bid & 31) * 256 * 4096,
                       g_gatesp2, 4096, 64, (bid >> 5) * 64, (bid & 31) * 128, bid >> 5);
        gridbar(++gen);
        cell_work(bid, b_ih, b_hh);
        gridbar(++gen);
        mma_phase_bulk(sb, gc, g_A2h,
                       g_Wh2 + (size_t)(bid & 7) * 64 * 4096,
                       g_hprojp2, 1024, 4, (bid >> 3) * 4, (bid & 7) * 128, bid >> 3);
        gridbar(++gen);
        if (bid < 32)
            attn_work(bid, s_hp, s_wl, x_enc, x_enc_k, xm, w_trg_b, w_att, w_att_b);
        else if (bid < 64 && t + 1 < TT)
            emb_prefetch(bid - 32, t + 1, word_emb, y_train);
        gridbar(++gen);
        mma_phase_bulk(sb, gc, g_A2p,
                       g_Wp2 + (size_t)(bid & 7) * 192 * 4096,
                       g_prep2, 1024, 12, (bid >> 3) * 12, (bid & 7) * 128, bid >> 3);
        gridbar(++gen);
    }
    pretanh_work(TT - 1, bid);
}

// ------------------- logits GEMM (unchanged, passing) -----------------------------------
__global__ void __launch_bounds__(256, 2) k_logits_mma(float* __restrict__ out) {
    __shared__ __align__(16) __nv_bfloat16 sA[2][128][40];
    __shared__ __align__(16) __nv_bfloat16 sB[2][128][40];
    int tid = threadIdx.x;
    int lane = tid & 31, wid = tid >> 5;
    int warpM = wid & 1, warpN = wid >> 1;
    int row0 = blockIdx.x * 128;
    int col0 = blockIdx.y * 128;

    int a_row = (lane & 7) + ((lane >> 3) & 1) * 8;
    int a_k   = (lane >> 4) * 8;
    int b_row = (lane & 7) + (lane >> 4) * 8;
    int b_k   = ((lane >> 3) & 1) * 8;
    uint32_t aBase = smem_u32(&sA[0][0][0]) + (warpM * 64 + a_row) * 80 + a_k * 2;
    uint32_t bBase = smem_u32(&sB[0][0][0]) + (warpN * 32 + b_row) * 80 + b_k * 2;

    int ldr = tid >> 2;
    int ldi = tid & 3;

    float acc[4][4][4];
#pragma unroll
    for (int i = 0; i < 4; i++)
#pragma unroll
        for (int j = 0; j < 4; j++)
#pragma unroll
            for (int q = 0; q < 4; q++) acc[i][j][q] = 0.f;

#pragma unroll
    for (int q = 0; q < 2; q++) {
        int r = ldr + q * 64;
        cpasync16(smem_u32(&sA[0][r][ldi * 8]), g_Abf + (size_t)(row0 + r) * KP + ldi * 8);
        cpasync16(smem_u32(&sB[0][r][ldi * 8]), g_Bbf + (size_t)(col0 + r) * KP + ldi * 8);
    }
    asm volatile("cp.async.commit_group;" ::: "memory");

    const int NCH = KP / 32;
    for (int i = 0; i < NCH; i++) {
        int st = i & 1;
        if (i + 1 < NCH) {
            int ns = st ^ 1;
            int kb = (i + 1) * 32;
#pragma unroll
            for (int q = 0; q < 2; q++) {
                int r = ldr + q * 64;
                cpasync16(smem_u32(&sA[ns][r][ldi * 8]),
                          g_Abf + (size_t)(row0 + r) * KP + kb + ldi * 8);
                cpasync16(smem_u32(&sB[ns][r][ldi * 8]),
                          g_Bbf + (size_t)(col0 + r) * KP + kb + ldi * 8);
            }
            asm volatile("cp.async.commit_group;" ::: "memory");
            asm volatile("cp.async.wait_group 1;" ::: "memory");
        } else {
            asm volatile("cp.async.wait_group 0;" ::: "memory");
        }
        __syncthreads();

        uint32_t stoff = st * (uint32_t)(128 * 80);
#pragma unroll
        for (int k16 = 0; k16 < 2; k16++) {
            uint32_t koff = stoff + k16 * 32;
            uint32_t a[4][4], b[2][4];
#pragma unroll
            for (int mt = 0; mt < 4; mt++) ldm_x4(a[mt], aBase + koff + mt * 1280);
#pragma unroll
            for (int p = 0; p < 2; p++)    ldm_x4(b[p], bBase + koff + p * 1280);
#pragma unroll
            for (int mt = 0; mt < 4; mt++)
#pragma unroll
                for (int nt = 0; nt < 4; nt++)
                    mma_bf16(acc[mt][nt], a[mt], &b[nt >> 1][(nt & 1) * 2]);
        }
        __syncthreads();
    }

    int grp = lane >> 2, tig = lane & 3;
#pragma unroll
    for (int mt = 0; mt < 4; mt++) {
        int m1 = row0 + warpM * 64 + mt * 16 + grp;
        int m2 = m1 + 8;
        float* o1 = out + ((size_t)(m1 & 31) * TT + (m1 >> 5)) * V;
        float* o2 = out + ((size_t)(m2 & 31) * TT + (m2 >> 5)) * V;
#pragma unroll
        for (int nt = 0; nt < 4; nt++) {
            int n = col0 + warpN * 32 + nt * 8 + tig * 2;
            *(float2*)(o1 + n) = make_float2(acc[mt][nt][0], acc[mt][nt][1]);
            *(float2*)(o2 + n) = make_float2(acc[mt][nt][2], acc[mt][nt][3]);
        }
    }
}

// ------------------- launch ---------------------------------------------------------------
extern "C" void kernel_launch(void* const* d_in, const int* in_sizes, int n_in,
                              void* d_out, int out_size) {
    const float* x_enc      = (const float*)d_in[0];
    const float* x_enc_k    = (const float*)d_in[1];
    const float* h0         = (const float*)d_in[2];
    const float* c0         = (const float*)d_in[3];
    const unsigned char* xm = (const unsigned char*)d_in[4];
    const int*   y_train    = (const int*)d_in[5];
    const float* word_emb   = (const float*)d_in[6];
    const float* W_ih       = (const float*)d_in[7];
    const float* W_hh       = (const float*)d_in[8];
    const float* b_ih       = (const float*)d_in[9];
    const float* b_hh       = (const float*)d_in[10];
    const float* w_trg_W    = (const float*)d_in[11];
    const float* w_trg_b    = (const float*)d_in[12];
    const float* w_att      = (const float*)d_in[13];
    const float* w_att_b    = (const float*)d_in[14];
    const float* ctx_W      = (const float*)d_in[15];
    const float* RW         = (const float*)d_in[16];
    float* out = (float*)d_out;

    k_convB<<<(V * D) / 256, 256>>>(RW);
    k_convWg<<<dim3(16, 4096), 256>>>(W_ih, W_hh);
    k_convWh<<<dim3(4, 1024), 256>>>(w_trg_W);
    k_convWp<<<dim3(12, 1024), 256>>>(ctx_W);
    int init_total = 64 * 8192 + 32 * 1024 + 32 * 3072 + B * D;
    k_init0<<<(init_total + 255) / 256, 256>>>(h0, c0, word_emb, y_train);
    k_steps<<<GRIDN, 256>>>(x_enc, x_enc_k, xm, y_train, word_emb,
                            b_ih, b_hh, w_trg_b, w_att, w_att_b);
    k_logits_mma<<<dim3((B * TT) / 128, V / 128), 256>>>(out);
}

// round 9
// speedup vs baseline: 1.1755x; 1.1755x over previous
#include <cuda_runtime.h>
#include <cuda_bf16.h>
#include <math.h>
#include <stdint.h>

#define B  32
#define LX 64
#define TT 64
#define D  1024
#define V  32000
#define KP 3072
#define GRIDN 128
// ring: 3 mbarriers (32B) | A stages 3x4096 | B stages 3x8192
#define ABASE 32
#define BBASE 12320
#define RINGSZ 36896

// ------------------- device globals --------------------------------------------
__device__ float g_c[B * D];
__device__ float g_gatesp2[4 * 64 * 4096];
__device__ float g_hprojp2[16 * 64 * 1024];
__device__ float g_prep2[16 * 64 * 1024];
// step-GEMM A operands, chunk-block layout [chunk][64][32] (4KB blocks)
__device__ __align__(16) __nv_bfloat16 g_A2g[256 * 64 * 32];
__device__ __align__(16) __nv_bfloat16 g_A2h[64 * 64 * 32];
__device__ __align__(16) __nv_bfloat16 g_A2p[192 * 64 * 32];
// logits operands (row-major)
__device__ __align__(16) __nv_bfloat16 g_Abf[(TT * B) * KP];
__device__ __align__(16) __nv_bfloat16 g_Bbf[(size_t)V * KP];
// weights, chunk-block layout [coltile][chunk][128][32] (8KB blocks)
__device__ __align__(16) __nv_bfloat16 g_Wg2[(size_t)32 * 256 * 128 * 32];
__device__ __align__(16) __nv_bfloat16 g_Wh2[8 * 64 * 128 * 32];
__device__ __align__(16) __nv_bfloat16 g_Wp2[8 * 192 * 128 * 32];
__device__ unsigned g_arrive;
__device__ volatile unsigned g_release;

// ------------------- helpers -----------------------------------------------------
__device__ __forceinline__ float fast_tanh(float x) {
    float e = __expf(2.f * x);
    return 1.f - __fdividef(2.f, e + 1.f);
}
__device__ __forceinline__ uint32_t smem_u32(const void* p) {
    uint32_t a;
    asm("{ .reg .u64 t; cvta.to.shared.u64 t, %1; cvt.u32.u64 %0, t; }" : "=r"(a) : "l"(p));
    return a;
}
__device__ __forceinline__ void cpasync16(uint32_t dst, const void* src) {
    asm volatile("cp.async.cg.shared.global [%0], [%1], 16;" :: "r"(dst), "l"(src));
}
__device__ __forceinline__ void ldm_x4(uint32_t* r, uint32_t addr) {
    asm volatile("ldmatrix.sync.aligned.m8n8.x4.shared.b16 {%0,%1,%2,%3}, [%4];"
        : "=r"(r[0]), "=r"(r[1]), "=r"(r[2]), "=r"(r[3]) : "r"(addr));
}
__device__ __forceinline__ void mma_bf16(float* c, const uint32_t* a, const uint32_t* b) {
    asm volatile("mma.sync.aligned.m16n8k16.row.col.f32.bf16.bf16.f32 "
        "{%0,%1,%2,%3}, {%4,%5,%6,%7}, {%8,%9}, {%0,%1,%2,%3};"
        : "+f"(c[0]), "+f"(c[1]), "+f"(c[2]), "+f"(c[3])
        : "r"(a[0]), "r"(a[1]), "r"(a[2]), "r"(a[3]), "r"(b[0]), "r"(b[1]));
}
__device__ __forceinline__ void split_bf(float v, __nv_bfloat16& hi, __nv_bfloat16& lo) {
    hi = __float2bfloat16_rn(v);
    lo = __float2bfloat16_rn(v - __bfloat162float(hi));
}
// swizzled element offset within a [row][32] chunk-block row
__device__ __forceinline__ int swoff(int row, int kin) {
    return ((((kin >> 3) ^ ((row >> 1) & 3)) << 3) | (kin & 7));
}
__device__ __forceinline__ void a2st(__nv_bfloat16* base, int row, int k, __nv_bfloat16 v) {
    base[((k >> 5) * 64 + row) * 32 + swoff(row, k & 31)] = v;
}
__device__ __forceinline__ void w2st(__nv_bfloat16* base, int nch, int j, int k,
                                     __nv_bfloat16 v) {
    base[(size_t)(((j >> 7) * nch + (k >> 5)) * 128 + (j & 127)) * 32
         + swoff(j & 127, k & 31)] = v;
}
// ------------------- bulk copy + mbarrier ------------------------------------------
__device__ __forceinline__ void bulk_g2s(uint32_t dst, const void* src, uint32_t bytes,
                                         uint32_t mbar) {
    asm volatile(
        "cp.async.bulk.shared::cluster.global.mbarrier::complete_tx::bytes [%0], [%1], %2, [%3];"
        :: "r"(dst), "l"(src), "r"(bytes), "r"(mbar) : "memory");
}
__device__ __forceinline__ void mbar_expect(uint32_t mbar, uint32_t bytes) {
    asm volatile("mbarrier.arrive.expect_tx.shared.b64 _, [%0], %1;"
                 :: "r"(mbar), "r"(bytes) : "memory");
}
__device__ __forceinline__ void mbar_init1(uint32_t mbar) {
    asm volatile("mbarrier.init.shared.b64 [%0], 1;" :: "r"(mbar) : "memory");
}
__device__ __forceinline__ void mbar_wait(uint32_t mbar, uint32_t parity) {
    asm volatile(
        "{\n\t.reg .pred P;\n"
        "W%=:\n\t"
        "mbarrier.try_wait.parity.shared.b64 P, [%0], %1;\n\t"
        "@P bra D%=;\n\t"
        "bra W%=;\n"
        "D%=:\n\t}"
        :: "r"(mbar), "r"(parity) : "memory");
}
// issue one (A,B) chunk pair into ring stage idx%3 (tid 0 only)
__device__ __forceinline__ void issue_chunk(uint32_t sb, unsigned idx,
        const __nv_bfloat16* __restrict__ Ablk,
        const __nv_bfloat16* __restrict__ Bblk, int chunk) {
    uint32_t st = idx % 3u, mb = sb + st * 8u;
    mbar_expect(mb, 12288u);
    bulk_g2s(sb + ABASE + st * 4096u, Ablk + (size_t)chunk * 2048, 4096u, mb);
    bulk_g2s(sb + BBASE + st * 8192u, Bblk + (size_t)chunk * 4096, 8192u, mb);
}
// ------------------- grid barrier ---------------------------------------------------
__device__ __forceinline__ void gridbar(unsigned gen) {
    asm volatile("fence.proxy.async;" ::: "memory");
    __threadfence();
    __syncthreads();
    if (threadIdx.x == 0) {
        unsigned a = atomicAdd(&g_arrive, 1u) + 1u;
        if (a == gen * GRIDN) {
            atomicExch((unsigned*)&g_release, gen);
        } else {
            while (g_release < gen) __nanosleep(32);
        }
    }
    __syncthreads();
}

// ------------------- init -----------------------------------------------------------
__global__ void k_init0(const float* __restrict__ h0, const float* __restrict__ c0,
                        const float* __restrict__ word_emb,
                        const int* __restrict__ y_train) {
    int i = blockIdx.x * 256 + threadIdx.x;
    if (i == 0) { g_arrive = 0; g_release = 0; }
    if (i < 64 * 8192) {                 // gates A2 for t=0
        int r = i >> 13, k = i & 8191;
        int b = r & 31;
        bool isLo = r >= 32;
        int ks = (k < 4096) ? k : k - 4096;
        float v = 0.f;
        bool zero = (isLo && k >= 4096);
        if (!zero) {
            if (ks < 1024) {
                int y = y_train[b * TT + 0];
                v = word_emb[(size_t)y * D + ks];
            } else if (ks < 3072) {
                v = 0.f;
            } else {
                v = h0[b * D + (ks - 3072)];
            }
        }
        __nv_bfloat16 hi, lo; split_bf(v, hi, lo);
        a2st(g_A2g, r, k, zero ? __float2bfloat16_rn(0.f) : (isLo ? lo : hi));
        return;
    }
    int j = i - 64 * 8192;
    if (j < 32 * 1024) {                 // A2h lo-zero rows 32-63, k [1024,2048)
        int r = 32 + (j >> 10), k = 1024 + (j & 1023);
        a2st(g_A2h, r, k, __float2bfloat16_rn(0.f));
        return;
    }
    j -= 32 * 1024;
    if (j < 32 * 3072) {                 // A2p lo-zero rows 32-63, k [3072,6144)
        int r = 32 + j / 3072, k = 3072 + j % 3072;
        a2st(g_A2p, r, k, __float2bfloat16_rn(0.f));
        return;
    }
    j -= 32 * 3072;
    if (j < B * D) g_c[j] = c0[j];
}

// ------------------- weight conversions ----------------------------------------------
__global__ void k_convB(const float* __restrict__ RW) {
    int i = blockIdx.x * 256 + threadIdx.x;
    float v = RW[i];
    int r = i >> 10, d = i & 1023;
    __nv_bfloat16 hi, lo; split_bf(v, hi, lo);
    __nv_bfloat16* row = g_Bbf + (size_t)r * KP;
    row[d] = hi; row[1024 + d] = hi; row[2048 + d] = lo;
}
__global__ void k_convWg(const float* __restrict__ Wih, const float* __restrict__ Whh) {
    int k = blockIdx.x * 256 + threadIdx.x;
    int j = blockIdx.y;
    float v = (k < 3072) ? Wih[(size_t)j * 3072 + k] : Whh[(size_t)j * 1024 + (k - 3072)];
    __nv_bfloat16 hi, lo; split_bf(v, hi, lo);
    w2st(g_Wg2, 256, j, k, hi);
    w2st(g_Wg2, 256, j, 4096 + k, lo);
}
__global__ void k_convWh(const float* __restrict__ Wt) {
    int k = blockIdx.x * 256 + threadIdx.x;
    int j = blockIdx.y;
    float v = Wt[(size_t)j * 1024 + k];
    __nv_bfloat16 hi, lo; split_bf(v, hi, lo);
    w2st(g_Wh2, 64, j, k, hi);
    w2st(g_Wh2, 64, j, 1024 + k, lo);
}
__global__ void k_convWp(const float* __restrict__ Cw) {
    int k = blockIdx.x * 256 + threadIdx.x;
    int j = blockIdx.y;
    float v = Cw[(size_t)j * 3072 + k];
    __nv_bfloat16 hi, lo; split_bf(v, hi, lo);
    w2st(g_Wp2, 192, j, k, hi);
    w2st(g_Wp2, 192, j, 3072 + k, lo);
}

// ------------------- bulk-fed 64xK @ Kx128 MMA phase ----------------------------------
__device__ void mma_phase_bulk(uint32_t sb, unsigned& gc,
        const __nv_bfloat16* __restrict__ Ablk,
        const __nv_bfloat16* __restrict__ Bblk,
        float* __restrict__ part, int ncols,
        int nch, int chunk0, int col0, int split, bool pre_issued) {
    int tid = threadIdx.x;
    int lane = tid & 31, wid = tid >> 5;
    int warpM = wid & 1, warpN = wid >> 1;

    int a_row = (lane & 7) + ((lane >> 3) & 1) * 8;
    int ca0 = lane >> 4;
    int b_row = (lane & 7) + (lane >> 4) * 8;
    int cb0 = (lane >> 3) & 1;
    int rA[2], sA_[2], rB[2], sB_[2];
#pragma unroll
    for (int mt = 0; mt < 2; mt++) {
        int r = warpM * 32 + mt * 16 + a_row;
        rA[mt] = r * 64; sA_[mt] = (r >> 1) & 3;
    }
#pragma unroll
    for (int p = 0; p < 2; p++) {
        int r = warpN * 32 + p * 16 + b_row;
        rB[p] = r * 64; sB_[p] = (r >> 1) & 3;
    }

    float acc[2][4][4] = {};

    if (!pre_issued && tid == 0) {
        issue_chunk(sb, gc, Ablk, Bblk, chunk0);
        issue_chunk(sb, gc + 1, Ablk, Bblk, chunk0 + 1);
    }
    for (int i = 0; i < nch; i++) {
        // issue i+2 BEFORE waiting on i (stage (i+2)%3 freed by syncthreads of i-1)
        if (i + 2 < nch && tid == 0)
            issue_chunk(sb, gc + (unsigned)(i + 2), Ablk, Bblk, chunk0 + i + 2);
        unsigned idx = gc + (unsigned)i;
        uint32_t st = idx % 3u;
        mbar_wait(sb + st * 8u, (idx / 3u) & 1u);
        uint32_t aOff = sb + ABASE + st * 4096u;
        uint32_t bOff = sb + BBASE + st * 8192u;
#pragma unroll
        for (int k16 = 0; k16 < 2; k16++) {
            int ca = ca0 + 2 * k16, cb = cb0 + 2 * k16;
            uint32_t a0[4], a1[4], bb[2][4];
            ldm_x4(a0, aOff + rA[0] + ((ca ^ sA_[0]) << 4));
            ldm_x4(a1, aOff + rA[1] + ((ca ^ sA_[1]) << 4));
            ldm_x4(bb[0], bOff + rB[0] + ((cb ^ sB_[0]) << 4));
            ldm_x4(bb[1], bOff + rB[1] + ((cb ^ sB_[1]) << 4));
#pragma unroll
            for (int nt = 0; nt < 4; nt++) {
                mma_bf16(acc[0][nt], a0, &bb[nt >> 1][(nt & 1) * 2]);
                mma_bf16(acc[1][nt], a1, &bb[nt >> 1][(nt & 1) * 2]);
            }
        }
        __syncthreads();
    }
    gc += (unsigned)nch;

    int grp = lane >> 2, tig = lane & 3;
#pragma unroll
    for (int mt = 0; mt < 2; mt++) {
        int m1 = warpM * 32 + mt * 16 + grp;
        int m2 = m1 + 8;
        float* p1 = part + (size_t)(split * 64 + m1) * ncols + col0 + warpN * 32;
        float* p2 = part + (size_t)(split * 64 + m2) * ncols + col0 + warpN * 32;
#pragma unroll
        for (int nt = 0; nt < 4; nt++) {
            int n = nt * 8 + tig * 2;
            *(float2*)(p1 + n) = make_float2(acc[mt][nt][0], acc[mt][nt][1]);
            *(float2*)(p2 + n) = make_float2(acc[mt][nt][2], acc[mt][nt][3]);
        }
    }
}

// ------------------- scalar phase work ------------------------------------------------
__device__ void emb_prefetch(int b, int tnext, const float* __restrict__ word_emb,
                             const int* __restrict__ y_train) {
    int d = threadIdx.x * 4;
    int y = y_train[b * TT + tnext];
    float4 v = *(const float4*)(word_emb + (size_t)y * D + d);
    float vv[4] = {v.x, v.y, v.z, v.w};
#pragma unroll
    for (int q = 0; q < 4; q++) {
        __nv_bfloat16 hi, lo; split_bf(vv[q], hi, lo);
        int k = d + q;
        a2st(g_A2g, b, k, hi); a2st(g_A2g, b, 4096 + k, hi); a2st(g_A2g, 32 + b, k, lo);
    }
}

__device__ void cell_work(int bid, int t, const float* __restrict__ b_ih,
                          const float* __restrict__ b_hh,
                          const float* __restrict__ word_emb,
                          const int* __restrict__ y_train) {
    int id = bid * 256 + threadIdx.x;
    int m = id >> 10, d = id & 1023;
    float ig = b_ih[d]        + b_hh[d];
    float fg = b_ih[1024 + d] + b_hh[1024 + d];
    float gg = b_ih[2048 + d] + b_hh[2048 + d];
    float og = b_ih[3072 + d] + b_hh[3072 + d];
#pragma unroll
    for (int s = 0; s < 4; s++) {
        const float* p0 = g_gatesp2 + (size_t)(s * 64 + m) * 4096;
        const float* p1 = g_gatesp2 + (size_t)(s * 64 + 32 + m) * 4096;
        ig += __ldcg(p0 + d)        + __ldcg(p1 + d);
        fg += __ldcg(p0 + 1024 + d) + __ldcg(p1 + 1024 + d);
        gg += __ldcg(p0 + 2048 + d) + __ldcg(p1 + 2048 + d);
        og += __ldcg(p0 + 3072 + d) + __ldcg(p1 + 3072 + d);
    }
    float si = 1.f / (1.f + expf(-ig));
    float sf = 1.f / (1.f + expf(-fg));
    float so = 1.f / (1.f + expf(-og));
    float c = sf * __ldcg(&g_c[id]) + si * tanhf(gg);
    g_c[id] = c;
    float h = so * tanhf(c);
    __nv_bfloat16 hh, hl; split_bf(h, hh, hl);
    a2st(g_A2h, m, d, hh);        a2st(g_A2h, m, 1024 + d, hh);  a2st(g_A2h, 32 + m, d, hl);
    a2st(g_A2p, m, d, hh);        a2st(g_A2p, m, 3072 + d, hh);  a2st(g_A2p, 32 + m, d, hl);
    a2st(g_A2g, m, 3072 + d, hh); a2st(g_A2g, m, 7168 + d, hh);
    a2st(g_A2g, 32 + m, 3072 + d, hl);
    // emb(t+1) prefetch folded into cell phase (A2g emb region is only read in phase 1)
    if (bid < 32 && t + 1 < TT) emb_prefetch(bid, t + 1, word_emb, y_train);
}

__device__ void pretanh_work(int t, int bid) {
    int id = bid * 256 + threadIdx.x;
    int m = id >> 10, d = id & 1023;
    float v = 0.f;
#pragma unroll
    for (int s = 0; s < 16; s++) {
        v += __ldcg(&g_prep2[(size_t)(s * 64 + m) * 1024 + d]);
        v += __ldcg(&g_prep2[(size_t)(s * 64 + 32 + m) * 1024 + d]);
    }
    v = tanhf(v);
    int row = t * B + m;
    __nv_bfloat16 hi, lo; split_bf(v, hi, lo);
    __nv_bfloat16* arow = g_Abf + (size_t)row * KP;
    arow[d] = hi; arow[1024 + d] = lo; arow[2048 + d] = hi;
}

// attention: 4 CTAs per batch row b = bid>>2; quarter = bid&3 owns 512 ctx dims.
// scores computed redundantly (identical in all 4 CTAs -> deterministic).
__device__ void attn_work(int bid, float* s_hp, float* s_wl,
                          const float* __restrict__ x_enc,
                          const float* __restrict__ x_enc_k,
                          const unsigned char* __restrict__ xm,
                          const float* __restrict__ w_trg_b,
                          const float* __restrict__ w_att,
                          const float* __restrict__ w_att_b) {
    int b = bid >> 2;
    int quarter = bid & 3;
    int tid = threadIdx.x;
    int lane = tid & 31, wd = tid >> 5;
    for (int d = tid; d < 1024; d += 256) {
        float sum = w_trg_b[d];
#pragma unroll
        for (int s = 0; s < 16; s++) {
            sum += __ldcg(&g_hprojp2[(size_t)(s * 64 + b) * 1024 + d]);
            sum += __ldcg(&g_hprojp2[(size_t)(s * 64 + 32 + b) * 1024 + d]);
        }
        s_hp[d] = sum;
    }
    __syncthreads();
    for (int l = wd; l < LX; l += 8) {
        const float* xk = x_enc_k + ((size_t)b * LX + l) * D;
        float s = 0.f;
#pragma unroll 8
        for (int i = 0; i < 32; i++) {
            int d = lane + i * 32;
            s += fast_tanh(xk[d] + s_hp[d]) * w_att[d];
        }
#pragma unroll
        for (int off = 16; off; off >>= 1) s += __shfl_xor_sync(0xffffffffu, s, off);
        if (lane == 0) {
            float tot = s + w_att_b[0];
            if (xm[b * LX + l]) tot = -1e9f;
            s_wl[l] = tot;
        }
    }
    __syncthreads();
    if (tid == 0) {
        float mx = -1e30f;
        for (int l = 0; l < LX; l++) mx = fmaxf(mx, s_wl[l]);
        float z = 0.f;
        for (int l = 0; l < LX; l++) { float e = expf(s_wl[l] - mx); s_wl[l] = e; z += e; }
        float inv = 1.f / z;
        for (int l = 0; l < LX; l++) s_wl[l] *= inv;
    }
    __syncthreads();
    // ctx over this CTA's 512-dim quarter; l-range halved across thread halves,
    // reduced via s_hp (free after scores).
    {
        int half = tid >> 7;                 // 0 or 1
        int dt = (tid & 127) * 4;            // 0..508
        int d2 = quarter * 512 + dt;
        const float* xe = x_enc + (size_t)b * LX * 2048 + d2;
        float f[4] = {0.f, 0.f, 0.f, 0.f};
        int l0 = half * 32;
#pragma unroll 8
        for (int l = l0; l < l0 + 32; l++) {
            float w = s_wl[l];
            float4 x0 = *(const float4*)(xe + (size_t)l * 2048);
            f[0] += w * x0.x; f[1] += w * x0.y; f[2] += w * x0.z; f[3] += w * x0.w;
        }
        if (half == 0) {
            *(float4*)&s_hp[dt] = make_float4(f[0], f[1], f[2], f[3]);
        }
        __syncthreads();
        if (half == 1) {
            float4 o = *(const float4*)&s_hp[dt];
            f[0] += o.x; f[1] += o.y; f[2] += o.z; f[3] += o.w;
#pragma unroll
            for (int q = 0; q < 4; q++) {
                int dd = 1024 + d2 + q;
                __nv_bfloat16 hi, lo; split_bf(f[q], hi, lo);
                a2st(g_A2p, b, dd, hi);   a2st(g_A2p, b, 3072 + dd, hi);
                a2st(g_A2p, 32 + b, dd, lo);
                a2st(g_A2g, b, dd, hi);   a2st(g_A2g, b, 4096 + dd, hi);
                a2st(g_A2g, 32 + b, dd, lo);
            }
        }
    }
}

// ------------------- persistent step kernel --------------------------------------------
__global__ void __launch_bounds__(256, 1) k_steps(
    const float* __restrict__ x_enc, const float* __restrict__ x_enc_k,
    const unsigned char* __restrict__ xm, const int* __restrict__ y_train,
    const float* __restrict__ word_emb,
    const float* __restrict__ b_ih, const float* __restrict__ b_hh,
    const float* __restrict__ w_trg_b, const float* __restrict__ w_att,
    const float* __restrict__ w_att_b) {
    __shared__ __align__(128) char s_ring[RINGSZ];
    __shared__ float s_hp[1024];
    __shared__ float s_wl[LX];
    uint32_t sb = smem_u32(s_ring);
    int bid = blockIdx.x;
    int tid = threadIdx.x;
    unsigned gen = 0, gc = 0;

    if (tid == 0) { mbar_init1(sb); mbar_init1(sb + 8); mbar_init1(sb + 16); }
    __syncthreads();

    const __nv_bfloat16* Wg = g_Wg2 + (size_t)(bid & 31) * 256 * 4096;
    int g_chunk0 = (bid >> 5) * 64;

    for (int t = 0; t < TT; t++) {
        // phase 1: issue first gates chunks, hide pretanh(t-1) under the load ramp
        if (tid == 0) {
            issue_chunk(sb, gc, g_A2g, Wg, g_chunk0);
            issue_chunk(sb, gc + 1, g_A2g, Wg, g_chunk0 + 1);
        }
        if (t > 0) pretanh_work(t - 1, bid);
        mma_phase_bulk(sb, gc, g_A2g, Wg, g_gatesp2, 4096, 64,
                       g_chunk0, (bid & 31) * 128, bid >> 5, true);
        gridbar(++gen);
        // phase 2: LSTM cell + emb(t+1) prefetch
        cell_work(bid, t, b_ih, b_hh, word_emb, y_train);
        gridbar(++gen);
        // phase 3: hproj MMA
        mma_phase_bulk(sb, gc, g_A2h,
                       g_Wh2 + (size_t)(bid & 7) * 64 * 4096,
                       g_hprojp2, 1024, 4, (bid >> 3) * 4, (bid & 7) * 128,
                       bid >> 3, false);
        gridbar(++gen);
        // phase 4: attention on ALL 128 CTAs (4 per batch row)
        attn_work(bid, s_hp, s_wl, x_enc, x_enc_k, xm, w_trg_b, w_att, w_att_b);
        gridbar(++gen);
        // phase 5: pre MMA
        mma_phase_bulk(sb, gc, g_A2p,
                       g_Wp2 + (size_t)(bid & 7) * 192 * 4096,
                       g_prep2, 1024, 12, (bid >> 3) * 12, (bid & 7) * 128,
                       bid >> 3, false);
        gridbar(++gen);
    }
    pretanh_work(TT - 1, bid);
}

// ------------------- logits GEMM (unchanged, passing) -----------------------------------
__global__ void __launch_bounds__(256, 2) k_logits_mma(float* __restrict__ out) {
    __shared__ __align__(16) __nv_bfloat16 sA[2][128][40];
    __shared__ __align__(16) __nv_bfloat16 sB[2][128][40];
    int tid = threadIdx.x;
    int lane = tid & 31, wid = tid >> 5;
    int warpM = wid & 1, warpN = wid >> 1;
    int row0 = blockIdx.x * 128;
    int col0 = blockIdx.y * 128;

    int a_row = (lane & 7) + ((lane >> 3) & 1) * 8;
    int a_k   = (lane >> 4) * 8;
    int b_row = (lane & 7) + (lane >> 4) * 8;
    int b_k   = ((lane >> 3) & 1) * 8;
    uint32_t aBase = smem_u32(&sA[0][0][0]) + (warpM * 64 + a_row) * 80 + a_k * 2;
    uint32_t bBase = smem_u32(&sB[0][0][0]) + (warpN * 32 + b_row) * 80 + b_k * 2;

    int ldr = tid >> 2;
    int ldi = tid & 3;

    float acc[4][4][4];
#pragma unroll
    for (int i = 0; i < 4; i++)
#pragma unroll
        for (int j = 0; j < 4; j++)
#pragma unroll
            for (int q = 0; q < 4; q++) acc[i][j][q] = 0.f;

#pragma unroll
    for (int q = 0; q < 2; q++) {
        int r = ldr + q * 64;
        cpasync16(smem_u32(&sA[0][r][ldi * 8]), g_Abf + (size_t)(row0 + r) * KP + ldi * 8);
        cpasync16(smem_u32(&sB[0][r][ldi * 8]), g_Bbf + (size_t)(col0 + r) * KP + ldi * 8);
    }
    asm volatile("cp.async.commit_group;" ::: "memory");

    const int NCH = KP / 32;
    for (int i = 0; i < NCH; i++) {
        int st = i & 1;
        if (i + 1 < NCH) {
            int ns = st ^ 1;
            int kb = (i + 1) * 32;
#pragma unroll
            for (int q = 0; q < 2; q++) {
                int r = ldr + q * 64;
                cpasync16(smem_u32(&sA[ns][r][ldi * 8]),
                          g_Abf + (size_t)(row0 + r) * KP + kb + ldi * 8);
                cpasync16(smem_u32(&sB[ns][r][ldi * 8]),
                          g_Bbf + (size_t)(col0 + r) * KP + kb + ldi * 8);
            }
            asm volatile("cp.async.commit_group;" ::: "memory");
            asm volatile("cp.async.wait_group 1;" ::: "memory");
        } else {
            asm volatile("cp.async.wait_group 0;" ::: "memory");
        }
        __syncthreads();

        uint32_t stoff = st * (uint32_t)(128 * 80);
#pragma unroll
        for (int k16 = 0; k16 < 2; k16++) {
            uint32_t koff = stoff + k16 * 32;
            uint32_t a[4][4], b[2][4];
#pragma unroll
            for (int mt = 0; mt < 4; mt++) ldm_x4(a[mt], aBase + koff + mt * 1280);
#pragma unroll
            for (int p = 0; p < 2; p++)    ldm_x4(b[p], bBase + koff + p * 1280);
#pragma unroll
            for (int mt = 0; mt < 4; mt++)
#pragma unroll
                for (int nt = 0; nt < 4; nt++)
                    mma_bf16(acc[mt][nt], a[mt], &b[nt >> 1][(nt & 1) * 2]);
        }
        __syncthreads();
    }

    int grp = lane >> 2, tig = lane & 3;
#pragma unroll
    for (int mt = 0; mt < 4; mt++) {
        int m1 = row0 + warpM * 64 + mt * 16 + grp;
        int m2 = m1 + 8;
        float* o1 = out + ((size_t)(m1 & 31) * TT + (m1 >> 5)) * V;
        float* o2 = out + ((size_t)(m2 & 31) * TT + (m2 >> 5)) * V;
#pragma unroll
        for (int nt = 0; nt < 4; nt++) {
            int n = col0 + warpN * 32 + nt * 8 + tig * 2;
            *(float2*)(o1 + n) = make_float2(acc[mt][nt][0], acc[mt][nt][1]);
            *(float2*)(o2 + n) = make_float2(acc[mt][nt][2], acc[mt][nt][3]);
        }
    }
}

// ------------------- launch ---------------------------------------------------------------
extern "C" void kernel_launch(void* const* d_in, const int* in_sizes, int n_in,
                              void* d_out, int out_size) {
    const float* x_enc      = (const float*)d_in[0];
    const float* x_enc_k    = (const float*)d_in[1];
    const float* h0         = (const float*)d_in[2];
    const float* c0         = (const float*)d_in[3];
    const unsigned char* xm = (const unsigned char*)d_in[4];
    const int*   y_train    = (const int*)d_in[5];
    const float* word_emb   = (const float*)d_in[6];
    const float* W_ih       = (const float*)d_in[7];
    const float* W_hh       = (const float*)d_in[8];
    const float* b_ih       = (const float*)d_in[9];
    const float* b_hh       = (const float*)d_in[10];
    const float* w_trg_W    = (const float*)d_in[11];
    const float* w_trg_b    = (const float*)d_in[12];
    const float* w_att      = (const float*)d_in[13];
    const float* w_att_b    = (const float*)d_in[14];
    const float* ctx_W      = (const float*)d_in[15];
    const float* RW         = (const float*)d_in[16];
    float* out = (float*)d_out;

    k_convB<<<(V * D) / 256, 256>>>(RW);
    k_convWg<<<dim3(16, 4096), 256>>>(W_ih, W_hh);
    k_convWh<<<dim3(4, 1024), 256>>>(w_trg_W);
    k_convWp<<<dim3(12, 1024), 256>>>(ctx_W);
    int init_total = 64 * 8192 + 32 * 1024 + 32 * 3072 + B * D;
    k_init0<<<(init_total + 255) / 256, 256>>>(h0, c0, word_emb, y_train);
    k_steps<<<GRIDN, 256>>>(x_enc, x_enc_k, xm, y_train, word_emb,
                            b_ih, b_hh, w_trg_b, w_att, w_att_b);
    k_logits_mma<<<dim3((B * TT) / 128, V / 128), 256>>>(out);
}

// round 10
// speedup vs baseline: 1.4002x; 1.1912x over previous
#include <cuda_runtime.h>
#include <cuda_bf16.h>
#include <math.h>
#include <stdint.h>

#define B  32
#define LX 64
#define TT 64
#define D  1024
#define V  32000
#define KP 3072
#define GRIDN 128
// ring: 3 mbarriers (32B) | A stages 3x4096 | B stages 3x8192
#define ABASE 32
#define BBASE 12320
#define RINGSZ 36896

// ------------------- device globals --------------------------------------------
__device__ float g_c[B * D];
__device__ float g_gatesp2[4 * 64 * 4096];
__device__ float g_hprojp2[16 * 64 * 1024];
__device__ float g_prep2[16 * 64 * 1024];
__device__ float g_wl[B * LX];                 // raw attention scores
// step-GEMM A operands, chunk-block layout [chunk][64][32] (4KB blocks)
__device__ __align__(16) __nv_bfloat16 g_A2g[256 * 64 * 32];
__device__ __align__(16) __nv_bfloat16 g_A2h[64 * 64 * 32];
__device__ __align__(16) __nv_bfloat16 g_A2p[192 * 64 * 32];
// logits operands (row-major)
__device__ __align__(16) __nv_bfloat16 g_Abf[(TT * B) * KP];
__device__ __align__(16) __nv_bfloat16 g_Bbf[(size_t)V * KP];
// weights, chunk-block layout [coltile][chunk][128][32] (8KB blocks)
__device__ __align__(16) __nv_bfloat16 g_Wg2[(size_t)32 * 256 * 128 * 32];
__device__ __align__(16) __nv_bfloat16 g_Wh2[8 * 64 * 128 * 32];
__device__ __align__(16) __nv_bfloat16 g_Wp2[8 * 192 * 128 * 32];
__device__ int g_flags[GRIDN];

// ------------------- helpers -----------------------------------------------------
__device__ __forceinline__ float fast_tanh(float x) {
    float e = __expf(2.f * x);
    return 1.f - __fdividef(2.f, e + 1.f);
}
__device__ __forceinline__ uint32_t smem_u32(const void* p) {
    uint32_t a;
    asm("{ .reg .u64 t; cvta.to.shared.u64 t, %1; cvt.u32.u64 %0, t; }" : "=r"(a) : "l"(p));
    return a;
}
__device__ __forceinline__ void cpasync16(uint32_t dst, const void* src) {
    asm volatile("cp.async.cg.shared.global [%0], [%1], 16;" :: "r"(dst), "l"(src));
}
__device__ __forceinline__ void ldm_x4(uint32_t* r, uint32_t addr) {
    asm volatile("ldmatrix.sync.aligned.m8n8.x4.shared.b16 {%0,%1,%2,%3}, [%4];"
        : "=r"(r[0]), "=r"(r[1]), "=r"(r[2]), "=r"(r[3]) : "r"(addr));
}
__device__ __forceinline__ void mma_bf16(float* c, const uint32_t* a, const uint32_t* b) {
    asm volatile("mma.sync.aligned.m16n8k16.row.col.f32.bf16.bf16.f32 "
        "{%0,%1,%2,%3}, {%4,%5,%6,%7}, {%8,%9}, {%0,%1,%2,%3};"
        : "+f"(c[0]), "+f"(c[1]), "+f"(c[2]), "+f"(c[3])
        : "r"(a[0]), "r"(a[1]), "r"(a[2]), "r"(a[3]), "r"(b[0]), "r"(b[1]));
}
__device__ __forceinline__ void split_bf(float v, __nv_bfloat16& hi, __nv_bfloat16& lo) {
    hi = __float2bfloat16_rn(v);
    lo = __float2bfloat16_rn(v - __bfloat162float(hi));
}
// swizzled element offset within a [row][32] chunk-block row
__device__ __forceinline__ int swoff(int row, int kin) {
    return ((((kin >> 3) ^ ((row >> 1) & 3)) << 3) | (kin & 7));
}
__device__ __forceinline__ void a2st(__nv_bfloat16* base, int row, int k, __nv_bfloat16 v) {
    base[((k >> 5) * 64 + row) * 32 + swoff(row, k & 31)] = v;
}
__device__ __forceinline__ void w2st(__nv_bfloat16* base, int nch, int j, int k,
                                     __nv_bfloat16 v) {
    base[(size_t)(((j >> 7) * nch + (k >> 5)) * 128 + (j & 127)) * 32
         + swoff(j & 127, k & 31)] = v;
}
// ------------------- bulk copy + mbarrier ------------------------------------------
__device__ __forceinline__ void bulk_g2s(uint32_t dst, const void* src, uint32_t bytes,
                                         uint32_t mbar) {
    asm volatile(
        "cp.async.bulk.shared::cluster.global.mbarrier::complete_tx::bytes [%0], [%1], %2, [%3];"
        :: "r"(dst), "l"(src), "r"(bytes), "r"(mbar) : "memory");
}
__device__ __forceinline__ void mbar_expect(uint32_t mbar, uint32_t bytes) {
    asm volatile("mbarrier.arrive.expect_tx.shared.b64 _, [%0], %1;"
                 :: "r"(mbar), "r"(bytes) : "memory");
}
__device__ __forceinline__ void mbar_init1(uint32_t mbar) {
    asm volatile("mbarrier.init.shared.b64 [%0], 1;" :: "r"(mbar) : "memory");
}
__device__ __forceinline__ void mbar_wait(uint32_t mbar, uint32_t parity) {
    asm volatile(
        "{\n\t.reg .pred P;\n"
        "W%=:\n\t"
        "mbarrier.try_wait.parity.shared.b64 P, [%0], %1;\n\t"
        "@P bra D%=;\n\t"
        "bra W%=;\n"
        "D%=:\n\t}"
        :: "r"(mbar), "r"(parity) : "memory");
}
// issue one (A,B) chunk pair into ring stage idx%3 (tid 0 only)
__device__ __forceinline__ void issue_chunk(uint32_t sb, unsigned idx,
        const __nv_bfloat16* __restrict__ Ablk,
        const __nv_bfloat16* __restrict__ Bblk, int chunk) {
    uint32_t st = idx % 3u, mb = sb + st * 8u;
    mbar_expect(mb, 12288u);
    bulk_g2s(sb + ABASE + st * 4096u, Ablk + (size_t)chunk * 2048, 4096u, mb);
    bulk_g2s(sb + BBASE + st * 8192u, Bblk + (size_t)chunk * 4096, 8192u, mb);
}
// ------------------- flag-array grid barrier -----------------------------------------
__device__ __forceinline__ void gridbar(unsigned gen) {
    asm volatile("fence.proxy.async;" ::: "memory");
    __threadfence();
    __syncthreads();
    if (threadIdx.x == 0) atomicExch(&g_flags[blockIdx.x], (int)gen);
    bool ok;
    do {
        ok = (threadIdx.x >= GRIDN) ||
             (__ldcg(&g_flags[threadIdx.x]) >= (int)gen);
    } while (!__syncthreads_and(ok));
}

// ------------------- init -----------------------------------------------------------
__global__ void k_init0(const float* __restrict__ h0, const float* __restrict__ c0,
                        const float* __restrict__ word_emb,
                        const int* __restrict__ y_train) {
    int i = blockIdx.x * 256 + threadIdx.x;
    if (i < GRIDN) g_flags[i] = 0;
    if (i < 64 * 8192) {                 // gates A2 for t=0
        int r = i >> 13, k = i & 8191;
        int b = r & 31;
        bool isLo = r >= 32;
        int ks = (k < 4096) ? k : k - 4096;
        float v = 0.f;
        bool zero = (isLo && k >= 4096);
        if (!zero) {
            if (ks < 1024) {
                int y = y_train[b * TT + 0];
                v = word_emb[(size_t)y * D + ks];
            } else if (ks < 3072) {
                v = 0.f;
            } else {
                v = h0[b * D + (ks - 3072)];
            }
        }
        __nv_bfloat16 hi, lo; split_bf(v, hi, lo);
        a2st(g_A2g, r, k, zero ? __float2bfloat16_rn(0.f) : (isLo ? lo : hi));
        return;
    }
    int j = i - 64 * 8192;
    if (j < 32 * 1024) {                 // A2h lo-zero rows 32-63, k [1024,2048)
        int r = 32 + (j >> 10), k = 1024 + (j & 1023);
        a2st(g_A2h, r, k, __float2bfloat16_rn(0.f));
        return;
    }
    j -= 32 * 1024;
    if (j < 32 * 3072) {                 // A2p lo-zero rows 32-63, k [3072,6144)
        int r = 32 + j / 3072, k = 3072 + j % 3072;
        a2st(g_A2p, r, k, __float2bfloat16_rn(0.f));
        return;
    }
    j -= 32 * 3072;
    if (j < B * D) g_c[j] = c0[j];
}

// ------------------- weight conversions ----------------------------------------------
__global__ void k_convB(const float* __restrict__ RW) {
    int i = blockIdx.x * 256 + threadIdx.x;
    float v = RW[i];
    int r = i >> 10, d = i & 1023;
    __nv_bfloat16 hi, lo; split_bf(v, hi, lo);
    __nv_bfloat16* row = g_Bbf + (size_t)r * KP;
    row[d] = hi; row[1024 + d] = hi; row[2048 + d] = lo;
}
__global__ void k_convWg(const float* __restrict__ Wih, const float* __restrict__ Whh) {
    int k = blockIdx.x * 256 + threadIdx.x;
    int j = blockIdx.y;
    float v = (k < 3072) ? Wih[(size_t)j * 3072 + k] : Whh[(size_t)j * 1024 + (k - 3072)];
    __nv_bfloat16 hi, lo; split_bf(v, hi, lo);
    w2st(g_Wg2, 256, j, k, hi);
    w2st(g_Wg2, 256, j, 4096 + k, lo);
}
__global__ void k_convWh(const float* __restrict__ Wt) {
    int k = blockIdx.x * 256 + threadIdx.x;
    int j = blockIdx.y;
    float v = Wt[(size_t)j * 1024 + k];
    __nv_bfloat16 hi, lo; split_bf(v, hi, lo);
    w2st(g_Wh2, 64, j, k, hi);
    w2st(g_Wh2, 64, j, 1024 + k, lo);
}
__global__ void k_convWp(const float* __restrict__ Cw) {
    int k = blockIdx.x * 256 + threadIdx.x;
    int j = blockIdx.y;
    float v = Cw[(size_t)j * 3072 + k];
    __nv_bfloat16 hi, lo; split_bf(v, hi, lo);
    w2st(g_Wp2, 192, j, k, hi);
    w2st(g_Wp2, 192, j, 3072 + k, lo);
}

// ------------------- bulk-fed 64xK @ Kx128 MMA phase ----------------------------------
__device__ void mma_phase_bulk(uint32_t sb, unsigned& gc,
        const __nv_bfloat16* __restrict__ Ablk,
        const __nv_bfloat16* __restrict__ Bblk,
        float* __restrict__ part, int ncols,
        int nch, int chunk0, int col0, int split, bool pre_issued) {
    int tid = threadIdx.x;
    int lane = tid & 31, wid = tid >> 5;
    int warpM = wid & 1, warpN = wid >> 1;

    int a_row = (lane & 7) + ((lane >> 3) & 1) * 8;
    int ca0 = lane >> 4;
    int b_row = (lane & 7) + (lane >> 4) * 8;
    int cb0 = (lane >> 3) & 1;
    int rA[2], sA_[2], rB[2], sB_[2];
#pragma unroll
    for (int mt = 0; mt < 2; mt++) {
        int r = warpM * 32 + mt * 16 + a_row;
        rA[mt] = r * 64; sA_[mt] = (r >> 1) & 3;
    }
#pragma unroll
    for (int p = 0; p < 2; p++) {
        int r = warpN * 32 + p * 16 + b_row;
        rB[p] = r * 64; sB_[p] = (r >> 1) & 3;
    }

    float acc[2][4][4] = {};

    if (!pre_issued && tid == 0) {
        issue_chunk(sb, gc, Ablk, Bblk, chunk0);
        issue_chunk(sb, gc + 1, Ablk, Bblk, chunk0 + 1);
    }
    for (int i = 0; i < nch; i++) {
        if (i + 2 < nch && tid == 0)
            issue_chunk(sb, gc + (unsigned)(i + 2), Ablk, Bblk, chunk0 + i + 2);
        unsigned idx = gc + (unsigned)i;
        uint32_t st = idx % 3u;
        mbar_wait(sb + st * 8u, (idx / 3u) & 1u);
        uint32_t aOff = sb + ABASE + st * 4096u;
        uint32_t bOff = sb + BBASE + st * 8192u;
#pragma unroll
        for (int k16 = 0; k16 < 2; k16++) {
            int ca = ca0 + 2 * k16, cb = cb0 + 2 * k16;
            uint32_t a0[4], a1[4], bb[2][4];
            ldm_x4(a0, aOff + rA[0] + ((ca ^ sA_[0]) << 4));
            ldm_x4(a1, aOff + rA[1] + ((ca ^ sA_[1]) << 4));
            ldm_x4(bb[0], bOff + rB[0] + ((cb ^ sB_[0]) << 4));
            ldm_x4(bb[1], bOff + rB[1] + ((cb ^ sB_[1]) << 4));
#pragma unroll
            for (int nt = 0; nt < 4; nt++) {
                mma_bf16(acc[0][nt], a0, &bb[nt >> 1][(nt & 1) * 2]);
                mma_bf16(acc[1][nt], a1, &bb[nt >> 1][(nt & 1) * 2]);
            }
        }
        __syncthreads();
    }
    gc += (unsigned)nch;

    int grp = lane >> 2, tig = lane & 3;
#pragma unroll
    for (int mt = 0; mt < 2; mt++) {
        int m1 = warpM * 32 + mt * 16 + grp;
        int m2 = m1 + 8;
        float* p1 = part + (size_t)(split * 64 + m1) * ncols + col0 + warpN * 32;
        float* p2 = part + (size_t)(split * 64 + m2) * ncols + col0 + warpN * 32;
#pragma unroll
        for (int nt = 0; nt < 4; nt++) {
            int n = nt * 8 + tig * 2;
            *(float2*)(p1 + n) = make_float2(acc[mt][nt][0], acc[mt][nt][1]);
            *(float2*)(p2 + n) = make_float2(acc[mt][nt][2], acc[mt][nt][3]);
        }
    }
}

// ------------------- scalar phase work ------------------------------------------------
__device__ void emb_prefetch(int b, int tnext, const float* __restrict__ word_emb,
                             const int* __restrict__ y_train) {
    int d = threadIdx.x * 4;
    int y = y_train[b * TT + tnext];
    float4 v = *(const float4*)(word_emb + (size_t)y * D + d);
    float vv[4] = {v.x, v.y, v.z, v.w};
#pragma unroll
    for (int q = 0; q < 4; q++) {
        __nv_bfloat16 hi, lo; split_bf(vv[q], hi, lo);
        int k = d + q;
        a2st(g_A2g, b, k, hi); a2st(g_A2g, b, 4096 + k, hi); a2st(g_A2g, 32 + b, k, lo);
    }
}

// vectorized LSTM cell: threads 0-63, 4 elements each (float4), s-order preserved
__device__ void cell_work(int bid, const float* __restrict__ b_ih,
                          const float* __restrict__ b_hh) {
    int tid = threadIdx.x;
    if (tid >= 64) return;
    int m = bid >> 2;
    int d = (bid & 3) * 256 + tid * 4;
    int id = m * 1024 + d;
    float gv[4][4];        // [gate][comp]
#pragma unroll
    for (int g = 0; g < 4; g++) {
        float4 bi = *(const float4*)(b_ih + g * 1024 + d);
        float4 bh = *(const float4*)(b_hh + g * 1024 + d);
        gv[g][0] = bi.x + bh.x; gv[g][1] = bi.y + bh.y;
        gv[g][2] = bi.z + bh.z; gv[g][3] = bi.w + bh.w;
    }
#pragma unroll
    for (int s = 0; s < 4; s++) {
#pragma unroll
        for (int g = 0; g < 4; g++) {
            float4 p0 = __ldcg((const float4*)(g_gatesp2
                         + (size_t)(s * 64 + m) * 4096 + g * 1024 + d));
            float4 p1 = __ldcg((const float4*)(g_gatesp2
                         + (size_t)(s * 64 + 32 + m) * 4096 + g * 1024 + d));
            gv[g][0] += p0.x; gv[g][0] += p1.x;
            gv[g][1] += p0.y; gv[g][1] += p1.y;
            gv[g][2] += p0.z; gv[g][2] += p1.z;
            gv[g][3] += p0.w; gv[g][3] += p1.w;
        }
    }
    float4 cold = __ldcg((const float4*)&g_c[id]);
    float co[4] = {cold.x, cold.y, cold.z, cold.w};
    float4 cnew;
    float* cn = (float*)&cnew;
#pragma unroll
    for (int q = 0; q < 4; q++) {
        float si = 1.f / (1.f + expf(-gv[0][q]));
        float sf = 1.f / (1.f + expf(-gv[1][q]));
        float so = 1.f / (1.f + expf(-gv[3][q]));
        float c = sf * co[q] + si * tanhf(gv[2][q]);
        cn[q] = c;
        float h = so * tanhf(c);
        __nv_bfloat16 hh, hl; split_bf(h, hh, hl);
        int dd = d + q;
        a2st(g_A2h, m, dd, hh);        a2st(g_A2h, m, 1024 + dd, hh);
        a2st(g_A2h, 32 + m, dd, hl);
        a2st(g_A2p, m, dd, hh);        a2st(g_A2p, m, 3072 + dd, hh);
        a2st(g_A2p, 32 + m, dd, hl);
        a2st(g_A2g, m, 3072 + dd, hh); a2st(g_A2g, m, 7168 + dd, hh);
        a2st(g_A2g, 32 + m, 3072 + dd, hl);
    }
    *(float4*)&g_c[id] = cnew;
}

// vectorized pretanh: threads 0-63, 4 elements each, s-order preserved
__device__ void pretanh_work(int t, int bid) {
    int tid = threadIdx.x;
    if (tid >= 64) return;
    int m = bid >> 2;
    int d = (bid & 3) * 256 + tid * 4;
    float v[4] = {0.f, 0.f, 0.f, 0.f};
#pragma unroll
    for (int s = 0; s < 16; s++) {
        float4 p0 = __ldcg((const float4*)(g_prep2 + (size_t)(s * 64 + m) * 1024 + d));
        float4 p1 = __ldcg((const float4*)(g_prep2 + (size_t)(s * 64 + 32 + m) * 1024 + d));
        v[0] += p0.x; v[0] += p1.x;
        v[1] += p0.y; v[1] += p1.y;
        v[2] += p0.z; v[2] += p1.z;
        v[3] += p0.w; v[3] += p1.w;
    }
    int row = t * B + m;
    __nv_bfloat16* arow = g_Abf + (size_t)row * KP;
#pragma unroll
    for (int q = 0; q < 4; q++) {
        float tv = tanhf(v[q]);
        __nv_bfloat16 hi, lo; split_bf(tv, hi, lo);
        int dd = d + q;
        arow[dd] = hi; arow[1024 + dd] = lo; arow[2048 + dd] = hi;
    }
}

// scores phase: 4 CTAs per batch row; quarter q computes l in [16q, 16q+16)
__device__ void attn_scores(int bid, float* s_hp,
                            const float* __restrict__ x_enc_k,
                            const unsigned char* __restrict__ xm,
                            const float* __restrict__ w_trg_b,
                            const float* __restrict__ w_att,
                            const float* __restrict__ w_att_b) {
    int b = bid >> 2;
    int q = bid & 3;
    int tid = threadIdx.x;
    int lane = tid & 31, wd = tid >> 5;
    // finalize hproj partials (vectorized, s-order preserved)
    {
        int d4 = tid * 4;
        float4 bi = *(const float4*)(w_trg_b + d4);
        float sum[4] = {bi.x, bi.y, bi.z, bi.w};
#pragma unroll
        for (int s = 0; s < 16; s++) {
            float4 p0 = __ldcg((const float4*)(g_hprojp2
                        + (size_t)(s * 64 + b) * 1024 + d4));
            float4 p1 = __ldcg((const float4*)(g_hprojp2
                        + (size_t)(s * 64 + 32 + b) * 1024 + d4));
            sum[0] += p0.x; sum[0] += p1.x;
            sum[1] += p0.y; sum[1] += p1.y;
            sum[2] += p0.z; sum[2] += p1.z;
            sum[3] += p0.w; sum[3] += p1.w;
        }
        *(float4*)&s_hp[d4] = make_float4(sum[0], sum[1], sum[2], sum[3]);
    }
    __syncthreads();
    for (int l = q * 16 + wd; l < q * 16 + 16; l += 8) {
        const float* xk = x_enc_k + ((size_t)(b * LX + l)) * D;
        float s = 0.f;
#pragma unroll 8
        for (int i = 0; i < 32; i++) {
            int d = lane + i * 32;
            s += fast_tanh(xk[d] + s_hp[d]) * w_att[d];
        }
#pragma unroll
        for (int off = 16; off; off >>= 1) s += __shfl_xor_sync(0xffffffffu, s, off);
        if (lane == 0) {
            float tot = s + w_att_b[0];
            if (xm[b * LX + l]) tot = -1e9f;
            g_wl[b * LX + l] = tot;
        }
    }
}

// ctx phase: softmax (serial, from g_wl) + per-quarter 512-dim ctx
__device__ void attn_ctx(int bid, float* s_hp, float* s_wl,
                         const float* __restrict__ x_enc) {
    int b = bid >> 2;
    int quarter = bid & 3;
    int tid = threadIdx.x;
    if (tid == 0) {
        float tmp[LX];
        float mx = -1e30f;
        for (int l = 0; l < LX; l++) {
            float v = __ldcg(&g_wl[b * LX + l]);
            tmp[l] = v;
            mx = fmaxf(mx, v);
        }
        float z = 0.f;
        for (int l = 0; l < LX; l++) { float e = expf(tmp[l] - mx); tmp[l] = e; z += e; }
        float inv = 1.f / z;
        for (int l = 0; l < LX; l++) s_wl[l] = tmp[l] * inv;
    }
    __syncthreads();
    {
        int half = tid >> 7;
        int dt = (tid & 127) * 4;
        int d2 = quarter * 512 + dt;
        const float* xe = x_enc + (size_t)b * LX * 2048 + d2;
        float f[4] = {0.f, 0.f, 0.f, 0.f};
        int l0 = half * 32;
#pragma unroll 8
        for (int l = l0; l < l0 + 32; l++) {
            float w = s_wl[l];
            float4 x0 = *(const float4*)(xe + (size_t)l * 2048);
            f[0] += w * x0.x; f[1] += w * x0.y; f[2] += w * x0.z; f[3] += w * x0.w;
        }
        if (half == 0) {
            *(float4*)&s_hp[dt] = make_float4(f[0], f[1], f[2], f[3]);
        }
        __syncthreads();
        if (half == 1) {
            float4 o = *(const float4*)&s_hp[dt];
            f[0] += o.x; f[1] += o.y; f[2] += o.z; f[3] += o.w;
#pragma unroll
            for (int q = 0; q < 4; q++) {
                int dd = 1024 + d2 + q;
                __nv_bfloat16 hi, lo; split_bf(f[q], hi, lo);
                a2st(g_A2p, b, dd, hi);   a2st(g_A2p, b, 3072 + dd, hi);
                a2st(g_A2p, 32 + b, dd, lo);
                a2st(g_A2g, b, dd, hi);   a2st(g_A2g, b, 4096 + dd, hi);
                a2st(g_A2g, 32 + b, dd, lo);
            }
        }
    }
}

// ------------------- persistent step kernel --------------------------------------------
__global__ void __launch_bounds__(256, 1) k_steps(
    const float* __restrict__ x_enc, const float* __restrict__ x_enc_k,
    const unsigned char* __restrict__ xm, const int* __restrict__ y_train,
    const float* __restrict__ word_emb,
    const float* __restrict__ b_ih, const float* __restrict__ b_hh,
    const float* __restrict__ w_trg_b, const float* __restrict__ w_att,
    const float* __restrict__ w_att_b) {
    __shared__ __align__(128) char s_ring[RINGSZ];
    __shared__ float s_hp[1024];
    __shared__ float s_wl[LX];
    uint32_t sb = smem_u32(s_ring);
    int bid = blockIdx.x;
    int tid = threadIdx.x;
    unsigned gen = 0, gc = 0;

    if (tid == 0) { mbar_init1(sb); mbar_init1(sb + 8); mbar_init1(sb + 16); }
    __syncthreads();

    const __nv_bfloat16* Wg = g_Wg2 + (size_t)(bid & 31) * 256 * 4096;
    int g_chunk0 = (bid >> 5) * 64;

    for (int t = 0; t < TT; t++) {
        // phase 1: gates MMA (no trailing barrier from phase 5 needed)
        if (tid == 0) {
            issue_chunk(sb, gc, g_A2g, Wg, g_chunk0);
            issue_chunk(sb, gc + 1, g_A2g, Wg, g_chunk0 + 1);
        }
        mma_phase_bulk(sb, gc, g_A2g, Wg, g_gatesp2, 4096, 64,
                       g_chunk0, (bid & 31) * 128, bid >> 5, true);
        gridbar(++gen);
        // phase 2: LSTM cell + pretanh(t-1) + emb(t+1)
        cell_work(bid, b_ih, b_hh);
        if (t > 0) pretanh_work(t - 1, bid);
        if (bid < 32 && t + 1 < TT) emb_prefetch(bid, t + 1, word_emb, y_train);
        gridbar(++gen);
        // phase 3: hproj MMA
        mma_phase_bulk(sb, gc, g_A2h,
                       g_Wh2 + (size_t)(bid & 7) * 64 * 4096,
                       g_hprojp2, 1024, 4, (bid >> 3) * 4, (bid & 7) * 128,
                       bid >> 3, false);
        gridbar(++gen);
        // phase 4a: scores (split 16 l per CTA)
        attn_scores(bid, s_hp, x_enc_k, xm, w_trg_b, w_att, w_att_b);
        gridbar(++gen);
        // phase 4b: softmax + ctx
        attn_ctx(bid, s_hp, s_wl, x_enc);
        gridbar(++gen);
        // phase 5: pre MMA (no trailing grid barrier)
        mma_phase_bulk(sb, gc, g_A2p,
                       g_Wp2 + (size_t)(bid & 7) * 192 * 4096,
                       g_prep2, 1024, 12, (bid >> 3) * 12, (bid & 7) * 128,
                       bid >> 3, false);
    }
    gridbar(++gen);
    pretanh_work(TT - 1, bid);
}

// ------------------- logits GEMM (unchanged, passing) -----------------------------------
__global__ void __launch_bounds__(256, 2) k_logits_mma(float* __restrict__ out) {
    __shared__ __align__(16) __nv_bfloat16 sA[2][128][40];
    __shared__ __align__(16) __nv_bfloat16 sB[2][128][40];
    int tid = threadIdx.x;
    int lane = tid & 31, wid = tid >> 5;
    int warpM = wid & 1, warpN = wid >> 1;
    int row0 = blockIdx.x * 128;
    int col0 = blockIdx.y * 128;

    int a_row = (lane & 7) + ((lane >> 3) & 1) * 8;
    int a_k   = (lane >> 4) * 8;
    int b_row = (lane & 7) + (lane >> 4) * 8;
    int b_k   = ((lane >> 3) & 1) * 8;
    uint32_t aBase = smem_u32(&sA[0][0][0]) + (warpM * 64 + a_row) * 80 + a_k * 2;
    uint32_t bBase = smem_u32(&sB[0][0][0]) + (warpN * 32 + b_row) * 80 + b_k * 2;

    int ldr = tid >> 2;
    int ldi = tid & 3;

    float acc[4][4][4];
#pragma unroll
    for (int i = 0; i < 4; i++)
#pragma unroll
        for (int j = 0; j < 4; j++)
#pragma unroll
            for (int q = 0; q < 4; q++) acc[i][j][q] = 0.f;

#pragma unroll
    for (int q = 0; q < 2; q++) {
        int r = ldr + q * 64;
        cpasync16(smem_u32(&sA[0][r][ldi * 8]), g_Abf + (size_t)(row0 + r) * KP + ldi * 8);
        cpasync16(smem_u32(&sB[0][r][ldi * 8]), g_Bbf + (size_t)(col0 + r) * KP + ldi * 8);
    }
    asm volatile("cp.async.commit_group;" ::: "memory");

    const int NCH = KP / 32;
    for (int i = 0; i < NCH; i++) {
        int st = i & 1;
        if (i + 1 < NCH) {
            int ns = st ^ 1;
            int kb = (i + 1) * 32;
#pragma unroll
            for (int q = 0; q < 2; q++) {
                int r = ldr + q * 64;
                cpasync16(smem_u32(&sA[ns][r][ldi * 8]),
                          g_Abf + (size_t)(row0 + r) * KP + kb + ldi * 8);
                cpasync16(smem_u32(&sB[ns][r][ldi * 8]),
                          g_Bbf + (size_t)(col0 + r) * KP + kb + ldi * 8);
            }
            asm volatile("cp.async.commit_group;" ::: "memory");
            asm volatile("cp.async.wait_group 1;" ::: "memory");
        } else {
            asm volatile("cp.async.wait_group 0;" ::: "memory");
        }
        __syncthreads();

        uint32_t stoff = st * (uint32_t)(128 * 80);
#pragma unroll
        for (int k16 = 0; k16 < 2; k16++) {
            uint32_t koff = stoff + k16 * 32;
            uint32_t a[4][4], b[2][4];
#pragma unroll
            for (int mt = 0; mt < 4; mt++) ldm_x4(a[mt], aBase + koff + mt * 1280);
#pragma unroll
            for (int p = 0; p < 2; p++)    ldm_x4(b[p], bBase + koff + p * 1280);
#pragma unroll
            for (int mt = 0; mt < 4; mt++)
#pragma unroll
                for (int nt = 0; nt < 4; nt++)
                    mma_bf16(acc[mt][nt], a[mt], &b[nt >> 1][(nt & 1) * 2]);
        }
        __syncthreads();
    }

    int grp = lane >> 2, tig = lane & 3;
#pragma unroll
    for (int mt = 0; mt < 4; mt++) {
        int m1 = row0 + warpM * 64 + mt * 16 + grp;
        int m2 = m1 + 8;
        float* o1 = out + ((size_t)(m1 & 31) * TT + (m1 >> 5)) * V;
        float* o2 = out + ((size_t)(m2 & 31) * TT + (m2 >> 5)) * V;
#pragma unroll
        for (int nt = 0; nt < 4; nt++) {
            int n = col0 + warpN * 32 + nt * 8 + tig * 2;
            *(float2*)(o1 + n) = make_float2(acc[mt][nt][0], acc[mt][nt][1]);
            *(float2*)(o2 + n) = make_float2(acc[mt][nt][2], acc[mt][nt][3]);
        }
    }
}

// ------------------- launch ---------------------------------------------------------------
extern "C" void kernel_launch(void* const* d_in, const int* in_sizes, int n_in,
                              void* d_out, int out_size) {
    const float* x_enc      = (const float*)d_in[0];
    const float* x_enc_k    = (const float*)d_in[1];
    const float* h0         = (const float*)d_in[2];
    const float* c0         = (const float*)d_in[3];
    const unsigned char* xm = (const unsigned char*)d_in[4];
    const int*   y_train    = (const int*)d_in[5];
    const float* word_emb   = (const float*)d_in[6];
    const float* W_ih       = (const float*)d_in[7];
    const float* W_hh       = (const float*)d_in[8];
    const float* b_ih       = (const float*)d_in[9];
    const float* b_hh       = (const float*)d_in[10];
    const float* w_trg_W    = (const float*)d_in[11];
    const float* w_trg_b    = (const float*)d_in[12];
    const float* w_att      = (const float*)d_in[13];
    const float* w_att_b    = (const float*)d_in[14];
    const float* ctx_W      = (const float*)d_in[15];
    const float* RW         = (const float*)d_in[16];
    float* out = (float*)d_out;

    k_convB<<<(V * D) / 256, 256>>>(RW);
    k_convWg<<<dim3(16, 4096), 256>>>(W_ih, W_hh);
    k_convWh<<<dim3(4, 1024), 256>>>(w_trg_W);
    k_convWp<<<dim3(12, 1024), 256>>>(ctx_W);
    int init_total = 64 * 8192 + 32 * 1024 + 32 * 3072 + B * D;
    k_init0<<<(init_total + 255) / 256, 256>>>(h0, c0, word_emb, y_train);
    k_steps<<<GRIDN, 256>>>(x_enc, x_enc_k, xm, y_train, word_emb,
                            b_ih, b_hh, w_trg_b, w_att, w_att_b);
    k_logits_mma<<<dim3((B * TT) / 128, V / 128), 256>>>(out);
}

// round 12
// speedup vs baseline: 1.5286x; 1.0917x over previous
#include <cuda_runtime.h>
#include <cuda_bf16.h>
#include <math.h>
#include <stdint.h>

#define B  32
#define LX 64
#define TT 64
#define D  1024
#define V  32000
#define KP 3072
#define GRIDN 128
// dynamic ring for k_steps: mbar@0 (32B) | A stages 3x8192 @32 | B stages 3x16384 @24608
#define SC_ABASE 32
#define SC_BBASE 24608
#define STEPS_DYN (32 + 3 * 8192 + 3 * 16384)

// ------------------- device globals --------------------------------------------
__device__ float g_c[B * D];
__device__ float g_gatesp2[4 * 64 * 4096];
__device__ float g_hprojp2[16 * 64 * 1024];
__device__ float g_prep2[16 * 64 * 1024];
__device__ float g_wl[B * LX];
// step-GEMM A operands, chunk-block layout [chunk][64][32] (4KB blocks)
__device__ __align__(16) __nv_bfloat16 g_A2g[256 * 64 * 32];
__device__ __align__(16) __nv_bfloat16 g_A2h[64 * 64 * 32];
__device__ __align__(16) __nv_bfloat16 g_A2p[192 * 64 * 32];
// logits operands (row-major)
__device__ __align__(16) __nv_bfloat16 g_Abf[(TT * B) * KP];
__device__ __align__(16) __nv_bfloat16 g_Bbf[(size_t)V * KP];
// weights, chunk-block layout [coltile][chunk][128][32] (8KB blocks)
__device__ __align__(16) __nv_bfloat16 g_Wg2[(size_t)32 * 256 * 128 * 32];
__device__ __align__(16) __nv_bfloat16 g_Wh2[8 * 64 * 128 * 32];
__device__ __align__(16) __nv_bfloat16 g_Wp2[8 * 192 * 128 * 32];
__device__ int g_flags[GRIDN];

// ------------------- helpers -----------------------------------------------------
__device__ __forceinline__ float fast_tanh(float x) {
    float e = __expf(2.f * x);
    return 1.f - __fdividef(2.f, e + 1.f);
}
__device__ __forceinline__ uint32_t smem_u32(const void* p) {
    uint32_t a;
    asm("{ .reg .u64 t; cvta.to.shared.u64 t, %1; cvt.u32.u64 %0, t; }" : "=r"(a) : "l"(p));
    return a;
}
__device__ __forceinline__ void cpasync16(uint32_t dst, const void* src) {
    asm volatile("cp.async.cg.shared.global [%0], [%1], 16;" :: "r"(dst), "l"(src));
}
__device__ __forceinline__ void ldm_x4(uint32_t* r, uint32_t addr) {
    asm volatile("ldmatrix.sync.aligned.m8n8.x4.shared.b16 {%0,%1,%2,%3}, [%4];"
        : "=r"(r[0]), "=r"(r[1]), "=r"(r[2]), "=r"(r[3]) : "r"(addr));
}
__device__ __forceinline__ void mma_bf16(float* c, const uint32_t* a, const uint32_t* b) {
    asm volatile("mma.sync.aligned.m16n8k16.row.col.f32.bf16.bf16.f32 "
        "{%0,%1,%2,%3}, {%4,%5,%6,%7}, {%8,%9}, {%0,%1,%2,%3};"
        : "+f"(c[0]), "+f"(c[1]), "+f"(c[2]), "+f"(c[3])
        : "r"(a[0]), "r"(a[1]), "r"(a[2]), "r"(a[3]), "r"(b[0]), "r"(b[1]));
}
__device__ __forceinline__ void split_bf(float v, __nv_bfloat16& hi, __nv_bfloat16& lo) {
    hi = __float2bfloat16_rn(v);
    lo = __float2bfloat16_rn(v - __bfloat162float(hi));
}
__device__ __forceinline__ int swoff(int row, int kin) {
    return ((((kin >> 3) ^ ((row >> 1) & 3)) << 3) | (kin & 7));
}
__device__ __forceinline__ void a2st(__nv_bfloat16* base, int row, int k, __nv_bfloat16 v) {
    base[((k >> 5) * 64 + row) * 32 + swoff(row, k & 31)] = v;
}
__device__ __forceinline__ void w2st(__nv_bfloat16* base, int nch, int j, int k,
                                     __nv_bfloat16 v) {
    base[(size_t)(((j >> 7) * nch + (k >> 5)) * 128 + (j & 127)) * 32
         + swoff(j & 127, k & 31)] = v;
}
// ------------------- bulk copy + mbarrier ------------------------------------------
__device__ __forceinline__ void bulk_g2s(uint32_t dst, const void* src, uint32_t bytes,
                                         uint32_t mbar) {
    asm volatile(
        "cp.async.bulk.shared::cluster.global.mbarrier::complete_tx::bytes [%0], [%1], %2, [%3];"
        :: "r"(dst), "l"(src), "r"(bytes), "r"(mbar) : "memory");
}
__device__ __forceinline__ void mbar_expect(uint32_t mbar, uint32_t bytes) {
    asm volatile("mbarrier.arrive.expect_tx.shared.b64 _, [%0], %1;"
                 :: "r"(mbar), "r"(bytes) : "memory");
}
__device__ __forceinline__ void mbar_init1(uint32_t mbar) {
    asm volatile("mbarrier.init.shared.b64 [%0], 1;" :: "r"(mbar) : "memory");
}
__device__ __forceinline__ void mbar_wait(uint32_t mbar, uint32_t parity) {
    asm volatile(
        "{\n\t.reg .pred P;\n"
        "W%=:\n\t"
        "mbarrier.try_wait.parity.shared.b64 P, [%0], %1;\n\t"
        "@P bra D%=;\n\t"
        "bra W%=;\n"
        "D%=:\n\t}"
        :: "r"(mbar), "r"(parity) : "memory");
}
// issue one SUPER-chunk (two contiguous 32-k blocks) into ring stage idx%3
__device__ __forceinline__ void issue_super(uint32_t sb, unsigned idx,
        const __nv_bfloat16* __restrict__ Ablk,
        const __nv_bfloat16* __restrict__ Bblk, int chunk) {
    uint32_t st = idx % 3u, mb = sb + st * 8u;
    mbar_expect(mb, 24576u);
    bulk_g2s(sb + SC_ABASE + st * 8192u, Ablk + (size_t)chunk * 2048, 8192u, mb);
    bulk_g2s(sb + SC_BBASE + st * 16384u, Bblk + (size_t)chunk * 4096, 16384u, mb);
}
// ------------------- flag-array grid barrier -----------------------------------------
__device__ __forceinline__ void gridbar(unsigned gen) {
    asm volatile("fence.proxy.async;" ::: "memory");
    __threadfence();
    __syncthreads();
    if (threadIdx.x == 0) atomicExch(&g_flags[blockIdx.x], (int)gen);
    bool ok;
    do {
        ok = (threadIdx.x >= GRIDN) ||
             (__ldcg(&g_flags[threadIdx.x]) >= (int)gen);
    } while (!__syncthreads_and(ok));
}

// ------------------- init -----------------------------------------------------------
__global__ void k_init0(const float* __restrict__ h0, const float* __restrict__ c0,
                        const float* __restrict__ word_emb,
                        const int* __restrict__ y_train) {
    int i = blockIdx.x * 256 + threadIdx.x;
    if (i < GRIDN) g_flags[i] = 0;
    if (i < 64 * 8192) {                 // gates A2 for t=0
        int r = i >> 13, k = i & 8191;
        int b = r & 31;
        bool isLo = r >= 32;
        int ks = (k < 4096) ? k : k - 4096;
        float v = 0.f;
        bool zero = (isLo && k >= 4096);
        if (!zero) {
            if (ks < 1024) {
                int y = y_train[b * TT + 0];
                v = word_emb[(size_t)y * D + ks];
            } else if (ks < 3072) {
                v = 0.f;
            } else {
                v = h0[b * D + (ks - 3072)];
            }
        }
        __nv_bfloat16 hi, lo; split_bf(v, hi, lo);
        a2st(g_A2g, r, k, zero ? __float2bfloat16_rn(0.f) : (isLo ? lo : hi));
        return;
    }
    int j = i - 64 * 8192;
    if (j < 32 * 1024) {
        int r = 32 + (j >> 10), k = 1024 + (j & 1023);
        a2st(g_A2h, r, k, __float2bfloat16_rn(0.f));
        return;
    }
    j -= 32 * 1024;
    if (j < 32 * 3072) {
        int r = 32 + j / 3072, k = 3072 + j % 3072;
        a2st(g_A2p, r, k, __float2bfloat16_rn(0.f));
        return;
    }
    j -= 32 * 3072;
    if (j < B * D) g_c[j] = c0[j];
}

// ------------------- weight conversions ----------------------------------------------
__global__ void k_convB(const float* __restrict__ RW) {
    int i = blockIdx.x * 256 + threadIdx.x;
    float v = RW[i];
    int r = i >> 10, d = i & 1023;
    __nv_bfloat16 hi, lo; split_bf(v, hi, lo);
    __nv_bfloat16* row = g_Bbf + (size_t)r * KP;
    row[d] = hi; row[1024 + d] = hi; row[2048 + d] = lo;
}
__global__ void k_convWg(const float* __restrict__ Wih, const float* __restrict__ Whh) {
    int k = blockIdx.x * 256 + threadIdx.x;
    int j = blockIdx.y;
    float v = (k < 3072) ? Wih[(size_t)j * 3072 + k] : Whh[(size_t)j * 1024 + (k - 3072)];
    __nv_bfloat16 hi, lo; split_bf(v, hi, lo);
    w2st(g_Wg2, 256, j, k, hi);
    w2st(g_Wg2, 256, j, 4096 + k, lo);
}
__global__ void k_convWh(const float* __restrict__ Wt) {
    int k = blockIdx.x * 256 + threadIdx.x;
    int j = blockIdx.y;
    float v = Wt[(size_t)j * 1024 + k];
    __nv_bfloat16 hi, lo; split_bf(v, hi, lo);
    w2st(g_Wh2, 64, j, k, hi);
    w2st(g_Wh2, 64, j, 1024 + k, lo);
}
__global__ void k_convWp(const float* __restrict__ Cw) {
    int k = blockIdx.x * 256 + threadIdx.x;
    int j = blockIdx.y;
    float v = Cw[(size_t)j * 3072 + k];
    __nv_bfloat16 hi, lo; split_bf(v, hi, lo);
    w2st(g_Wp2, 192, j, k, hi);
    w2st(g_Wp2, 192, j, 3072 + k, lo);
}

// ------------------- super-chunk 64xK @ Kx128 MMA phase -------------------------------
__device__ void mma_phase_bulk(uint32_t sb, unsigned& gsc,
        const __nv_bfloat16* __restrict__ Ablk,
        const __nv_bfloat16* __restrict__ Bblk,
        float* __restrict__ part, int ncols,
        int nsuper, int chunk0, int col0, int split, bool pre_issued) {
    int tid = threadIdx.x;
    int lane = tid & 31, wid = tid >> 5;
    int warpM = wid & 1, warpN = wid >> 1;

    int a_row = (lane & 7) + ((lane >> 3) & 1) * 8;
    int ca0 = lane >> 4;
    int b_row = (lane & 7) + (lane >> 4) * 8;
    int cb0 = (lane >> 3) & 1;
    int rA[2], sA_[2], rB[2], sB_[2];
#pragma unroll
    for (int mt = 0; mt < 2; mt++) {
        int r = warpM * 32 + mt * 16 + a_row;
        rA[mt] = r * 64; sA_[mt] = (r >> 1) & 3;
    }
#pragma unroll
    for (int p = 0; p < 2; p++) {
        int r = warpN * 32 + p * 16 + b_row;
        rB[p] = r * 64; sB_[p] = (r >> 1) & 3;
    }

    float acc[2][4][4] = {};

    if (!pre_issued && tid == 0) {
        issue_super(sb, gsc, Ablk, Bblk, chunk0);
        if (nsuper > 1) issue_super(sb, gsc + 1, Ablk, Bblk, chunk0 + 2);
    }
    for (int i = 0; i < nsuper; i++) {
        if (i + 2 < nsuper && tid == 0)
            issue_super(sb, gsc + (unsigned)(i + 2), Ablk, Bblk, chunk0 + 2 * (i + 2));
        unsigned idx = gsc + (unsigned)i;
        uint32_t st = idx % 3u;
        mbar_wait(sb + st * 8u, (idx / 3u) & 1u);
#pragma unroll
        for (int sub = 0; sub < 2; sub++) {
            uint32_t aOff = sb + SC_ABASE + st * 8192u + sub * 4096u;
            uint32_t bOff = sb + SC_BBASE + st * 16384u + sub * 8192u;
#pragma unroll
            for (int k16 = 0; k16 < 2; k16++) {
                int ca = ca0 + 2 * k16, cb = cb0 + 2 * k16;
                uint32_t a0[4], a1[4], bb[2][4];
                ldm_x4(a0, aOff + rA[0] + ((ca ^ sA_[0]) << 4));
                ldm_x4(a1, aOff + rA[1] + ((ca ^ sA_[1]) << 4));
                ldm_x4(bb[0], bOff + rB[0] + ((cb ^ sB_[0]) << 4));
                ldm_x4(bb[1], bOff + rB[1] + ((cb ^ sB_[1]) << 4));
#pragma unroll
                for (int nt = 0; nt < 4; nt++) {
                    mma_bf16(acc[0][nt], a0, &bb[nt >> 1][(nt & 1) * 2]);
                    mma_bf16(acc[1][nt], a1, &bb[nt >> 1][(nt & 1) * 2]);
                }
            }
        }
        __syncthreads();
    }
    gsc += (unsigned)nsuper;

    int grp = lane >> 2, tig = lane & 3;
#pragma unroll
    for (int mt = 0; mt < 2; mt++) {
        int m1 = warpM * 32 + mt * 16 + grp;
        int m2 = m1 + 8;
        float* p1 = part + (size_t)(split * 64 + m1) * ncols + col0 + warpN * 32;
        float* p2 = part + (size_t)(split * 64 + m2) * ncols + col0 + warpN * 32;
#pragma unroll
        for (int nt = 0; nt < 4; nt++) {
            int n = nt * 8 + tig * 2;
            *(float2*)(p1 + n) = make_float2(acc[mt][nt][0], acc[mt][nt][1]);
            *(float2*)(p2 + n) = make_float2(acc[mt][nt][2], acc[mt][nt][3]);
        }
    }
}

// ------------------- scalar phase work ------------------------------------------------
__device__ void emb_prefetch(int b, int tnext, const float* __restrict__ word_emb,
                             const int* __restrict__ y_train) {
    int d = threadIdx.x * 4;
    int y = y_train[b * TT + tnext];
    float4 v = *(const float4*)(word_emb + (size_t)y * D + d);
    float vv[4] = {v.x, v.y, v.z, v.w};
#pragma unroll
    for (int q = 0; q < 4; q++) {
        __nv_bfloat16 hi, lo; split_bf(vv[q], hi, lo);
        int k = d + q;
        a2st(g_A2g, b, k, hi); a2st(g_A2g, b, 4096 + k, hi); a2st(g_A2g, 32 + b, k, lo);
    }
}

__device__ void cell_work(int bid, const float* __restrict__ b_ih,
                          const float* __restrict__ b_hh) {
    int tid = threadIdx.x;
    if (tid >= 64) return;
    int m = bid >> 2;
    int d = (bid & 3) * 256 + tid * 4;
    int id = m * 1024 + d;
    float gv[4][4];
#pragma unroll
    for (int g = 0; g < 4; g++) {
        float4 bi = *(const float4*)(b_ih + g * 1024 + d);
        float4 bh = *(const float4*)(b_hh + g * 1024 + d);
        gv[g][0] = bi.x + bh.x; gv[g][1] = bi.y + bh.y;
        gv[g][2] = bi.z + bh.z; gv[g][3] = bi.w + bh.w;
    }
#pragma unroll
    for (int s = 0; s < 4; s++) {
#pragma unroll
        for (int g = 0; g < 4; g++) {
            float4 p0 = __ldcg((const float4*)(g_gatesp2
                         + (size_t)(s * 64 + m) * 4096 + g * 1024 + d));
            float4 p1 = __ldcg((const float4*)(g_gatesp2
                         + (size_t)(s * 64 + 32 + m) * 4096 + g * 1024 + d));
            gv[g][0] += p0.x; gv[g][0] += p1.x;
            gv[g][1] += p0.y; gv[g][1] += p1.y;
            gv[g][2] += p0.z; gv[g][2] += p1.z;
            gv[g][3] += p0.w; gv[g][3] += p1.w;
        }
    }
    float4 cold = __ldcg((const float4*)&g_c[id]);
    float co[4] = {cold.x, cold.y, cold.z, cold.w};
    float4 cnew;
    float* cn = (float*)&cnew;
#pragma unroll
    for (int q = 0; q < 4; q++) {
        float si = 1.f / (1.f + expf(-gv[0][q]));
        float sf = 1.f / (1.f + expf(-gv[1][q]));
        float so = 1.f / (1.f + expf(-gv[3][q]));
        float c = sf * co[q] + si * tanhf(gv[2][q]);
        cn[q] = c;
        float h = so * tanhf(c);
        __nv_bfloat16 hh, hl; split_bf(h, hh, hl);
        int dd = d + q;
        a2st(g_A2h, m, dd, hh);        a2st(g_A2h, m, 1024 + dd, hh);
        a2st(g_A2h, 32 + m, dd, hl);
        a2st(g_A2p, m, dd, hh);        a2st(g_A2p, m, 3072 + dd, hh);
        a2st(g_A2p, 32 + m, dd, hl);
        a2st(g_A2g, m, 3072 + dd, hh); a2st(g_A2g, m, 7168 + dd, hh);
        a2st(g_A2g, 32 + m, 3072 + dd, hl);
    }
    *(float4*)&g_c[id] = cnew;
}

__device__ void pretanh_work(int t, int bid) {
    int tid = threadIdx.x;
    if (tid >= 64) return;
    int m = bid >> 2;
    int d = (bid & 3) * 256 + tid * 4;
    float v[4] = {0.f, 0.f, 0.f, 0.f};
#pragma unroll
    for (int s = 0; s < 16; s++) {
        float4 p0 = __ldcg((const float4*)(g_prep2 + (size_t)(s * 64 + m) * 1024 + d));
        float4 p1 = __ldcg((const float4*)(g_prep2 + (size_t)(s * 64 + 32 + m) * 1024 + d));
        v[0] += p0.x; v[0] += p1.x;
        v[1] += p0.y; v[1] += p1.y;
        v[2] += p0.z; v[2] += p1.z;
        v[3] += p0.w; v[3] += p1.w;
    }
    int row = t * B + m;
    __nv_bfloat16* arow = g_Abf + (size_t)row * KP;
#pragma unroll
    for (int q = 0; q < 4; q++) {
        float tv = tanhf(v[q]);
        __nv_bfloat16 hi, lo; split_bf(tv, hi, lo);
        int dd = d + q;
        arow[dd] = hi; arow[1024 + dd] = lo; arow[2048 + dd] = hi;
    }
}

__device__ void attn_scores(int bid, float* s_hp,
                            const float* __restrict__ x_enc_k,
                            const unsigned char* __restrict__ xm,
                            const float* __restrict__ w_trg_b,
                            const float* __restrict__ w_att,
                            const float* __restrict__ w_att_b) {
    int b = bid >> 2;
    int q = bid & 3;
    int tid = threadIdx.x;
    int lane = tid & 31, wd = tid >> 5;
    {
        int d4 = tid * 4;
        float4 bi = *(const float4*)(w_trg_b + d4);
        float sum[4] = {bi.x, bi.y, bi.z, bi.w};
#pragma unroll
        for (int s = 0; s < 16; s++) {
            float4 p0 = __ldcg((const float4*)(g_hprojp2
                        + (size_t)(s * 64 + b) * 1024 + d4));
            float4 p1 = __ldcg((const float4*)(g_hprojp2
                        + (size_t)(s * 64 + 32 + b) * 1024 + d4));
            sum[0] += p0.x; sum[0] += p1.x;
            sum[1] += p0.y; sum[1] += p1.y;
            sum[2] += p0.z; sum[2] += p1.z;
            sum[3] += p0.w; sum[3] += p1.w;
        }
        *(float4*)&s_hp[d4] = make_float4(sum[0], sum[1], sum[2], sum[3]);
    }
    __syncthreads();
    for (int l = q * 16 + wd; l < q * 16 + 16; l += 8) {
        const float* xk = x_enc_k + ((size_t)(b * LX + l)) * D;
        float s = 0.f;
#pragma unroll 8
        for (int i = 0; i < 32; i++) {
            int d = lane + i * 32;
            s += fast_tanh(xk[d] + s_hp[d]) * w_att[d];
        }
#pragma unroll
        for (int off = 16; off; off >>= 1) s += __shfl_xor_sync(0xffffffffu, s, off);
        if (lane == 0) {
            float tot = s + w_att_b[0];
            if (xm[b * LX + l]) tot = -1e9f;
            g_wl[b * LX + l] = tot;
        }
    }
}

__device__ void attn_ctx(int bid, float* s_hp, float* s_wl,
                         const float* __restrict__ x_enc) {
    int b = bid >> 2;
    int quarter = bid & 3;
    int tid = threadIdx.x;
    if (tid == 0) {
        float tmp[LX];
        float mx = -1e30f;
        for (int l = 0; l < LX; l++) {
            float v = __ldcg(&g_wl[b * LX + l]);
            tmp[l] = v;
            mx = fmaxf(mx, v);
        }
        float z = 0.f;
        for (int l = 0; l < LX; l++) { float e = expf(tmp[l] - mx); tmp[l] = e; z += e; }
        float inv = 1.f / z;
        for (int l = 0; l < LX; l++) s_wl[l] = tmp[l] * inv;
    }
    __syncthreads();
    {
        int half = tid >> 7;
        int dt = (tid & 127) * 4;
        int d2 = quarter * 512 + dt;
        const float* xe = x_enc + (size_t)b * LX * 2048 + d2;
        float f[4] = {0.f, 0.f, 0.f, 0.f};
        int l0 = half * 32;
#pragma unroll 8
        for (int l = l0; l < l0 + 32; l++) {
            float w = s_wl[l];
            float4 x0 = *(const float4*)(xe + (size_t)l * 2048);
            f[0] += w * x0.x; f[1] += w * x0.y; f[2] += w * x0.z; f[3] += w * x0.w;
        }
        if (half == 0) {
            *(float4*)&s_hp[dt] = make_float4(f[0], f[1], f[2], f[3]);
        }
        __syncthreads();
        if (half == 1) {
            float4 o = *(const float4*)&s_hp[dt];
            f[0] += o.x; f[1] += o.y; f[2] += o.z; f[3] += o.w;
#pragma unroll
            for (int q = 0; q < 4; q++) {
                int dd = 1024 + d2 + q;
                __nv_bfloat16 hi, lo; split_bf(f[q], hi, lo);
                a2st(g_A2p, b, dd, hi);   a2st(g_A2p, b, 3072 + dd, hi);
                a2st(g_A2p, 32 + b, dd, lo);
                a2st(g_A2g, b, dd, hi);   a2st(g_A2g, b, 4096 + dd, hi);
                a2st(g_A2g, 32 + b, dd, lo);
            }
        }
    }
}

// ------------------- persistent step kernel --------------------------------------------
__global__ void __launch_bounds__(256, 1) k_steps(
    const float* __restrict__ x_enc, const float* __restrict__ x_enc_k,
    const unsigned char* __restrict__ xm, const int* __restrict__ y_train,
    const float* __restrict__ word_emb,
    const float* __restrict__ b_ih, const float* __restrict__ b_hh,
    const float* __restrict__ w_trg_b, const float* __restrict__ w_att,
    const float* __restrict__ w_att_b) {
    extern __shared__ __align__(128) char s_ring[];
    __shared__ float s_hp[1024];
    __shared__ float s_wl[LX];
    uint32_t sb = smem_u32(s_ring);
    int bid = blockIdx.x;
    int tid = threadIdx.x;
    unsigned gen = 0, gsc = 0;

    if (tid == 0) { mbar_init1(sb); mbar_init1(sb + 8); mbar_init1(sb + 16); }
    __syncthreads();

    const __nv_bfloat16* Wg = g_Wg2 + (size_t)(bid & 31) * 256 * 4096;
    int g_chunk0 = (bid >> 5) * 64;

    for (int t = 0; t < TT; t++) {
        // phase 1: gates MMA (32 super-chunks)
        if (tid == 0) {
            issue_super(sb, gsc, g_A2g, Wg, g_chunk0);
            issue_super(sb, gsc + 1, g_A2g, Wg, g_chunk0 + 2);
        }
        mma_phase_bulk(sb, gsc, g_A2g, Wg, g_gatesp2, 4096, 32,
                       g_chunk0, (bid & 31) * 128, bid >> 5, true);
        gridbar(++gen);
        // phase 2: LSTM cell + pretanh(t-1) + emb(t+1)
        cell_work(bid, b_ih, b_hh);
        if (t > 0) pretanh_work(t - 1, bid);
        if (bid < 32 && t + 1 < TT) emb_prefetch(bid, t + 1, word_emb, y_train);
        gridbar(++gen);
        // phase 3: hproj MMA (2 super-chunks)
        mma_phase_bulk(sb, gsc, g_A2h,
                       g_Wh2 + (size_t)(bid & 7) * 64 * 4096,
                       g_hprojp2, 1024, 2, (bid >> 3) * 4, (bid & 7) * 128,
                       bid >> 3, false);
        gridbar(++gen);
        // phase 4a: scores
        attn_scores(bid, s_hp, x_enc_k, xm, w_trg_b, w_att, w_att_b);
        gridbar(++gen);
        // phase 4b: softmax + ctx
        attn_ctx(bid, s_hp, s_wl, x_enc);
        gridbar(++gen);
        // phase 5: pre MMA (6 super-chunks, no trailing barrier)
        mma_phase_bulk(sb, gsc, g_A2p,
                       g_Wp2 + (size_t)(bid & 7) * 192 * 4096,
                       g_prep2, 1024, 6, (bid >> 3) * 12, (bid & 7) * 128,
                       bid >> 3, false);
    }
    gridbar(++gen);
    pretanh_work(TT - 1, bid);
}

// ------------------- logits GEMM (EXACT R10 version, known passing) ----------------------
__global__ void __launch_bounds__(256, 2) k_logits_mma(float* __restrict__ out) {
    __shared__ __align__(16) __nv_bfloat16 sA[2][128][40];
    __shared__ __align__(16) __nv_bfloat16 sB[2][128][40];
    int tid = threadIdx.x;
    int lane = tid & 31, wid = tid >> 5;
    int warpM = wid & 1, warpN = wid >> 1;
    int row0 = blockIdx.x * 128;
    int col0 = blockIdx.y * 128;

    int a_row = (lane & 7) + ((lane >> 3) & 1) * 8;
    int a_k   = (lane >> 4) * 8;
    int b_row = (lane & 7) + (lane >> 4) * 8;
    int b_k   = ((lane >> 3) & 1) * 8;
    uint32_t aBase = smem_u32(&sA[0][0][0]) + (warpM * 64 + a_row) * 80 + a_k * 2;
    uint32_t bBase = smem_u32(&sB[0][0][0]) + (warpN * 32 + b_row) * 80 + b_k * 2;

    int ldr = tid >> 2;
    int ldi = tid & 3;

    float acc[4][4][4];
#pragma unroll
    for (int i = 0; i < 4; i++)
#pragma unroll
        for (int j = 0; j < 4; j++)
#pragma unroll
            for (int q = 0; q < 4; q++) acc[i][j][q] = 0.f;

#pragma unroll
    for (int q = 0; q < 2; q++) {
        int r = ldr + q * 64;
        cpasync16(smem_u32(&sA[0][r][ldi * 8]), g_Abf + (size_t)(row0 + r) * KP + ldi * 8);
        cpasync16(smem_u32(&sB[0][r][ldi * 8]), g_Bbf + (size_t)(col0 + r) * KP + ldi * 8);
    }
    asm volatile("cp.async.commit_group;" ::: "memory");

    const int NCH = KP / 32;
    for (int i = 0; i < NCH; i++) {
        int st = i & 1;
        if (i + 1 < NCH) {
            int ns = st ^ 1;
            int kb = (i + 1) * 32;
#pragma unroll
            for (int q = 0; q < 2; q++) {
                int r = ldr + q * 64;
                cpasync16(smem_u32(&sA[ns][r][ldi * 8]),
                          g_Abf + (size_t)(row0 + r) * KP + kb + ldi * 8);
                cpasync16(smem_u32(&sB[ns][r][ldi * 8]),
                          g_Bbf + (size_t)(col0 + r) * KP + kb + ldi * 8);
            }
            asm volatile("cp.async.commit_group;" ::: "memory");
            asm volatile("cp.async.wait_group 1;" ::: "memory");
        } else {
            asm volatile("cp.async.wait_group 0;" ::: "memory");
        }
        __syncthreads();

        uint32_t stoff = st * (uint32_t)(128 * 80);
#pragma unroll
        for (int k16 = 0; k16 < 2; k16++) {
            uint32_t koff = stoff + k16 * 32;
            uint32_t a[4][4], b[2][4];
#pragma unroll
            for (int mt = 0; mt < 4; mt++) ldm_x4(a[mt], aBase + koff + mt * 1280);
#pragma unroll
            for (int p = 0; p < 2; p++)    ldm_x4(b[p], bBase + koff + p * 1280);
#pragma unroll
            for (int mt = 0; mt < 4; mt++)
#pragma unroll
                for (int nt = 0; nt < 4; nt++)
                    mma_bf16(acc[mt][nt], a[mt], &b[nt >> 1][(nt & 1) * 2]);
        }
        __syncthreads();
    }

    int grp = lane >> 2, tig = lane & 3;
#pragma unroll
    for (int mt = 0; mt < 4; mt++) {
        int m1 = row0 + warpM * 64 + mt * 16 + grp;
        int m2 = m1 + 8;
        float* o1 = out + ((size_t)(m1 & 31) * TT + (m1 >> 5)) * V;
        float* o2 = out + ((size_t)(m2 & 31) * TT + (m2 >> 5)) * V;
#pragma unroll
        for (int nt = 0; nt < 4; nt++) {
            int n = col0 + warpN * 32 + nt * 8 + tig * 2;
            *(float2*)(o1 + n) = make_float2(acc[mt][nt][0], acc[mt][nt][1]);
            *(float2*)(o2 + n) = make_float2(acc[mt][nt][2], acc[mt][nt][3]);
        }
    }
}

// ------------------- launch ---------------------------------------------------------------
extern "C" void kernel_launch(void* const* d_in, const int* in_sizes, int n_in,
                              void* d_out, int out_size) {
    const float* x_enc      = (const float*)d_in[0];
    const float* x_enc_k    = (const float*)d_in[1];
    const float* h0         = (const float*)d_in[2];
    const float* c0         = (const float*)d_in[3];
    const unsigned char* xm = (const unsigned char*)d_in[4];
    const int*   y_train    = (const int*)d_in[5];
    const float* word_emb   = (const float*)d_in[6];
    const float* W_ih       = (const float*)d_in[7];
    const float* W_hh       = (const float*)d_in[8];
    const float* b_ih       = (const float*)d_in[9];
    const float* b_hh       = (const float*)d_in[10];
    const float* w_trg_W    = (const float*)d_in[11];
    const float* w_trg_b    = (const float*)d_in[12];
    const float* w_att      = (const float*)d_in[13];
    const float* w_att_b    = (const float*)d_in[14];
    const float* ctx_W      = (const float*)d_in[15];
    const float* RW         = (const float*)d_in[16];
    float* out = (float*)d_out;

    cudaFuncSetAttribute(k_steps, cudaFuncAttributeMaxDynamicSharedMemorySize, STEPS_DYN);

    k_convB<<<(V * D) / 256, 256>>>(RW);
    k_convWg<<<dim3(16, 4096), 256>>>(W_ih, W_hh);
    k_convWh<<<dim3(4, 1024), 256>>>(w_trg_W);
    k_convWp<<<dim3(12, 1024), 256>>>(ctx_W);
    int init_total = 64 * 8192 + 32 * 1024 + 32 * 3072 + B * D;
    k_init0<<<(init_total + 255) / 256, 256>>>(h0, c0, word_emb, y_train);
    k_steps<<<GRIDN, 256, STEPS_DYN>>>(x_enc, x_enc_k, xm, y_train, word_emb,
                                       b_ih, b_hh, w_trg_b, w_att, w_att_b);
    k_logits_mma<<<dim3((B * TT) / 128, V / 128), 256>>>(out);
}